// round 1
// baseline (speedup 1.0000x reference)
#include <cuda_runtime.h>
#include <cstdint>
#include <cstddef>

#define NNODES 4096
#define INDIM 256
#define HID 64

// ---------------- scratch (no allocation allowed) ----------------
__device__ float g_wh1[4 * NNODES * HID];   // [H][N][64]
__device__ float g_src1[4 * NNODES];
__device__ float g_dst1[4 * NNODES];
__device__ float g_x2[NNODES * 256];        // concat(elu(heads)) [N][256]
__device__ float g_wh2[NNODES * HID];       // [1][N][64]
__device__ float g_src2[NNODES];
__device__ float g_dst2[NNODES];

// ---------------- GEMM: Y[h][i][d] = sum_k X[i][k] * W[h][k][d] + B[h][d] ----
// X: [4096][256], W: [H][256][64], B: [H][64], Y: [H][4096][64]
// grid: (64, H), block: 256. Tile 64i x 64d, per-thread 4x4.
__global__ void gemm_bias_kernel(const float* __restrict__ X,
                                 const float* __restrict__ W,
                                 const float* __restrict__ B,
                                 float* __restrict__ Y)
{
    const int h  = blockIdx.y;
    const int i0 = blockIdx.x * 64;
    const int t  = threadIdx.x;
    const int dg = t & 15;       // 16 d-groups of 4 dims
    const int ig = t >> 4;       // 16 i-groups of 4 rows

    __shared__ float Xs[16][68]; // [k][i_local], padded; 272B row -> float4 aligned
    __shared__ float Ws[16][64]; // [k][d]

    float acc[4][4] = {};
    const float* Wh = W + (size_t)h * INDIM * HID;

    for (int kc = 0; kc < INDIM; kc += 16) {
        // stage X tile (transpose to [k][i])
        {
            int row = t >> 2, kq = t & 3;
            float4 v = *(const float4*)(X + (size_t)(i0 + row) * INDIM + kc + kq * 4);
            Xs[kq * 4 + 0][row] = v.x;
            Xs[kq * 4 + 1][row] = v.y;
            Xs[kq * 4 + 2][row] = v.z;
            Xs[kq * 4 + 3][row] = v.w;
        }
        // stage W tile
        {
            int kr = t >> 4, dq = t & 15;
            float4 v = *(const float4*)(Wh + (size_t)(kc + kr) * HID + dq * 4);
            *(float4*)(&Ws[kr][dq * 4]) = v;
        }
        __syncthreads();
        #pragma unroll
        for (int k = 0; k < 16; k++) {
            float4 xv = *(const float4*)(&Xs[k][ig * 4]);
            float4 wv = *(const float4*)(&Ws[k][dg * 4]);
            acc[0][0] += xv.x * wv.x; acc[0][1] += xv.x * wv.y; acc[0][2] += xv.x * wv.z; acc[0][3] += xv.x * wv.w;
            acc[1][0] += xv.y * wv.x; acc[1][1] += xv.y * wv.y; acc[1][2] += xv.y * wv.z; acc[1][3] += xv.y * wv.w;
            acc[2][0] += xv.z * wv.x; acc[2][1] += xv.z * wv.y; acc[2][2] += xv.z * wv.z; acc[2][3] += xv.z * wv.w;
            acc[3][0] += xv.w * wv.x; acc[3][1] += xv.w * wv.y; acc[3][2] += xv.w * wv.z; acc[3][3] += xv.w * wv.w;
        }
        __syncthreads();
    }

    float4 bv = *(const float4*)(B + h * HID + dg * 4);
    #pragma unroll
    for (int ii = 0; ii < 4; ii++) {
        float4 r;
        r.x = acc[ii][0] + bv.x;
        r.y = acc[ii][1] + bv.y;
        r.z = acc[ii][2] + bv.z;
        r.w = acc[ii][3] + bv.w;
        float* yp = Y + ((size_t)h * NNODES + i0 + ig * 4 + ii) * HID + dg * 4;
        *(float4*)yp = r;
    }
}

// ---------------- src/dst projections: warp per (h,i) row --------------------
__global__ void srcdst_kernel(const float* __restrict__ wh,
                              const float* __restrict__ asrc,
                              const float* __restrict__ adst,
                              float* __restrict__ osrc,
                              float* __restrict__ odst,
                              int total /* H*4096 */)
{
    int gw = (blockIdx.x * blockDim.x + threadIdx.x) >> 5;
    int lane = threadIdx.x & 31;
    if (gw >= total) return;
    int h = gw >> 12;            // 4096 rows per head
    const float* row = wh + (size_t)gw * HID;
    float v0 = row[lane], v1 = row[lane + 32];
    float s = v0 * asrc[h * HID + lane] + v1 * asrc[h * HID + lane + 32];
    float d = v0 * adst[h * HID + lane] + v1 * adst[h * HID + lane + 32];
    #pragma unroll
    for (int o = 16; o > 0; o >>= 1) {
        s += __shfl_xor_sync(0xffffffffu, s, o);
        d += __shfl_xor_sync(0xffffffffu, d, o);
    }
    if (lane == 0) { osrc[gw] = s; odst[gw] = d; }
}

// ---------------- fused attention: softmax(leaky(src_i+dst_j+b) | adj) @ wh --
// grid: (N/32, H), block: 128. Block owns 32 rows of one head.
// Output: out[i][colOff(h)..+63] = elu(att @ wh), colOff = h*64.
__global__ void attn_kernel(const float* __restrict__ wh,    // [H][N][64]
                            const float* __restrict__ ssrc,  // [H][N]
                            const float* __restrict__ sdst,  // [H][N]
                            const float* __restrict__ ab,    // [H]
                            const int*  __restrict__ adj,    // [N][N]
                            float* __restrict__ out,
                            int outStride)
{
    const int h  = blockIdx.y;
    const int i0 = blockIdx.x * 32;
    const int t  = threadIdx.x;          // 0..127
    const int lane = t & 31;
    const int w    = t >> 5;             // warp 0..3
    const int dg = t & 15;               // phase2: 16 d-groups * 4 dims
    const int ig = t >> 4;               // phase2: 8 i-groups * 4 rows

    __shared__ float whs[32][64];        // staged wh chunk [j][d]
    __shared__ float Es[32][33];         // exp scores [i_local][j_local]
    __shared__ float srcs[32];
    __shared__ float den[32];

    const float* whh = wh + (size_t)h * NNODES * HID;
    if (t < 32) srcs[t] = ssrc[h * NNODES + i0 + t] + ab[h];

    float acc[4][4] = {};
    float dsum0=0.f,dsum1=0.f,dsum2=0.f,dsum3=0.f,dsum4=0.f,dsum5=0.f,dsum6=0.f,dsum7=0.f;
    __syncthreads();

    for (int jc = 0; jc < NNODES; jc += 32) {
        // stage wh chunk: 32x64 floats = 512 float4, 4 per thread
        {
            const float4* s4 = (const float4*)(whh + (size_t)jc * HID);
            float4* d4 = (float4*)(&whs[0][0]);
            #pragma unroll
            for (int q = 0; q < 4; q++) d4[t + 128 * q] = s4[t + 128 * q];
        }
        // scores: warp w owns rows i0 + w*8 .. +7 (exclusive -> no atomics)
        float dstj = sdst[h * NNODES + jc + lane];
        #pragma unroll
        for (int k = 0; k < 8; k++) {
            int il = w * 8 + k;
            int a = adj[(size_t)(i0 + il) * NNODES + jc + lane];
            float s = srcs[il] + dstj;
            s = fmaxf(s, 0.2f * s);                 // leaky_relu(0.2)
            float e = (a > 0) ? __expf(s) : 0.0f;   // mask == softmax over NEG
            Es[il][lane] = e;
            #pragma unroll
            for (int o = 16; o > 0; o >>= 1) e += __shfl_xor_sync(0xffffffffu, e, o);
            if (k == 0) dsum0 += e; else if (k == 1) dsum1 += e;
            else if (k == 2) dsum2 += e; else if (k == 3) dsum3 += e;
            else if (k == 4) dsum4 += e; else if (k == 5) dsum5 += e;
            else if (k == 6) dsum6 += e; else dsum7 += e;
        }
        __syncthreads();
        // accumulate: per-thread 4i x 4d register tile over the 32-j chunk
        #pragma unroll 8
        for (int j = 0; j < 32; j++) {
            float4 wv = *(const float4*)(&whs[j][dg * 4]);
            float e0 = Es[ig * 4 + 0][j];
            float e1 = Es[ig * 4 + 1][j];
            float e2 = Es[ig * 4 + 2][j];
            float e3 = Es[ig * 4 + 3][j];
            acc[0][0] += e0 * wv.x; acc[0][1] += e0 * wv.y; acc[0][2] += e0 * wv.z; acc[0][3] += e0 * wv.w;
            acc[1][0] += e1 * wv.x; acc[1][1] += e1 * wv.y; acc[1][2] += e1 * wv.z; acc[1][3] += e1 * wv.w;
            acc[2][0] += e2 * wv.x; acc[2][1] += e2 * wv.y; acc[2][2] += e2 * wv.z; acc[2][3] += e2 * wv.w;
            acc[3][0] += e3 * wv.x; acc[3][1] += e3 * wv.y; acc[3][2] += e3 * wv.z; acc[3][3] += e3 * wv.w;
        }
        __syncthreads();
    }

    // publish denominators (warp w wrote rows w*8..w*8+7; all lanes hold the sum)
    if (lane == 0) {
        den[w * 8 + 0] = dsum0; den[w * 8 + 1] = dsum1;
        den[w * 8 + 2] = dsum2; den[w * 8 + 3] = dsum3;
        den[w * 8 + 4] = dsum4; den[w * 8 + 5] = dsum5;
        den[w * 8 + 6] = dsum6; den[w * 8 + 7] = dsum7;
    }
    __syncthreads();

    const int colOff = h * 64;
    #pragma unroll
    for (int ii = 0; ii < 4; ii++) {
        int i = i0 + ig * 4 + ii;
        float inv = 1.0f / den[ig * 4 + ii];
        float v[4];
        #pragma unroll
        for (int c = 0; c < 4; c++) {
            float x = acc[ii][c] * inv;
            v[c] = (x > 0.0f) ? x : expm1f(x);      // elu
        }
        float4 r; r.x = v[0]; r.y = v[1]; r.z = v[2]; r.w = v[3];
        *(float4*)(out + (size_t)i * outStride + colOff + dg * 4) = r;
    }
}

// ---------------- launch ------------------------------------------------------
extern "C" void kernel_launch(void* const* d_in, const int* in_sizes, int n_in,
                              void* d_out, int out_size)
{
    const float* h      = (const float*)d_in[0];
    const int*   adj    = (const int*)  d_in[1];
    const float* Wh     = (const float*)d_in[2];
    const float* bWh    = (const float*)d_in[3];
    const float* a_src  = (const float*)d_in[4];
    const float* a_dst  = (const float*)d_in[5];
    const float* a_b    = (const float*)d_in[6];
    const float* Wo     = (const float*)d_in[7];
    const float* bWo    = (const float*)d_in[8];
    const float* ao_src = (const float*)d_in[9];
    const float* ao_dst = (const float*)d_in[10];
    const float* ao_b   = (const float*)d_in[11];
    float* out = (float*)d_out;

    float *wh1, *src1, *dst1, *x2, *wh2, *src2, *dst2;
    cudaGetSymbolAddress((void**)&wh1,  g_wh1);
    cudaGetSymbolAddress((void**)&src1, g_src1);
    cudaGetSymbolAddress((void**)&dst1, g_dst1);
    cudaGetSymbolAddress((void**)&x2,   g_x2);
    cudaGetSymbolAddress((void**)&wh2,  g_wh2);
    cudaGetSymbolAddress((void**)&src2, g_src2);
    cudaGetSymbolAddress((void**)&dst2, g_dst2);

    // Layer 1
    gemm_bias_kernel<<<dim3(NNODES / 64, 4), 256>>>(h, Wh, bWh, wh1);
    srcdst_kernel<<<4 * 512, 256>>>(wh1, a_src, a_dst, src1, dst1, 4 * NNODES);
    attn_kernel<<<dim3(NNODES / 32, 4), 128>>>(wh1, src1, dst1, a_b, adj, x2, 256);

    // Layer 2
    gemm_bias_kernel<<<dim3(NNODES / 64, 1), 256>>>(x2, Wo, bWo, wh2);
    srcdst_kernel<<<512, 256>>>(wh2, ao_src, ao_dst, src2, dst2, NNODES);
    attn_kernel<<<dim3(NNODES / 32, 1), 128>>>(wh2, src2, dst2, ao_b, adj, out, 64);
}

// round 3
// speedup vs baseline: 1.5817x; 1.5817x over previous
#include <cuda_runtime.h>
#include <cstdint>
#include <cstddef>

#define NNODES 4096
#define INDIM 256
#define HID 64

// ---------------- scratch (no allocation allowed) ----------------
__device__ float g_wh1[4 * NNODES * HID];    // [H][N][64]
__device__ float g_src1[4 * NNODES];
__device__ float g_dst1[4 * NNODES];
__device__ float g_x2[NNODES * 256];         // concat heads [N][256]
__device__ float g_wh2[NNODES * HID];
__device__ float g_src2[NNODES];
__device__ float g_dst2[NNODES];
__device__ float g_pnum[4 * NNODES * HID];   // layer2 j-split partial numerators
__device__ float g_pden[4 * NNODES];         // layer2 j-split partial denominators

// ---------------- helpers ------------------------------------------------------
__device__ __forceinline__ uint32_t cvt_tf32(float x) {
    uint32_t r; asm("cvt.rna.tf32.f32 %0, %1;" : "=r"(r) : "f"(x)); return r;
}

__device__ __forceinline__ void mma1688(float* c,
                                        uint32_t a0, uint32_t a1, uint32_t a2, uint32_t a3,
                                        uint32_t b0, uint32_t b1) {
    asm volatile(
        "mma.sync.aligned.m16n8k8.row.col.f32.tf32.tf32.f32 "
        "{%0,%1,%2,%3}, {%4,%5,%6,%7}, {%8,%9}, {%0,%1,%2,%3};"
        : "+f"(c[0]), "+f"(c[1]), "+f"(c[2]), "+f"(c[3])
        : "r"(a0), "r"(a1), "r"(a2), "r"(a3), "r"(b0), "r"(b1));
}

// ---------------- GEMM: Y = X@W + B -------------------------------------------
// X: [4096][IN], W: [H][IN][64], Y: [H][4096][64]. grid (64, H), block 256.
__global__ void gemm_bias_kernel(const float* __restrict__ X,
                                 const float* __restrict__ W,
                                 const float* __restrict__ B,
                                 float* __restrict__ Y)
{
    const int h  = blockIdx.y;
    const int i0 = blockIdx.x * 64;
    const int t  = threadIdx.x;
    const int dg = t & 15;
    const int ig = t >> 4;

    __shared__ float Xs[16][68];
    __shared__ float Ws[16][64];

    float acc[4][4] = {};
    const float* Wh = W + (size_t)h * INDIM * HID;

    for (int kc = 0; kc < INDIM; kc += 16) {
        {
            int row = t >> 2, kq = t & 3;
            float4 v = *(const float4*)(X + (size_t)(i0 + row) * INDIM + kc + kq * 4);
            Xs[kq * 4 + 0][row] = v.x;
            Xs[kq * 4 + 1][row] = v.y;
            Xs[kq * 4 + 2][row] = v.z;
            Xs[kq * 4 + 3][row] = v.w;
        }
        {
            int kr = t >> 4, dq = t & 15;
            float4 v = *(const float4*)(Wh + (size_t)(kc + kr) * HID + dq * 4);
            *(float4*)(&Ws[kr][dq * 4]) = v;
        }
        __syncthreads();
        #pragma unroll
        for (int k = 0; k < 16; k++) {
            float4 xv = *(const float4*)(&Xs[k][ig * 4]);
            float4 wv = *(const float4*)(&Ws[k][dg * 4]);
            acc[0][0] += xv.x * wv.x; acc[0][1] += xv.x * wv.y; acc[0][2] += xv.x * wv.z; acc[0][3] += xv.x * wv.w;
            acc[1][0] += xv.y * wv.x; acc[1][1] += xv.y * wv.y; acc[1][2] += xv.y * wv.z; acc[1][3] += xv.y * wv.w;
            acc[2][0] += xv.z * wv.x; acc[2][1] += xv.z * wv.y; acc[2][2] += xv.z * wv.z; acc[2][3] += xv.z * wv.w;
            acc[3][0] += xv.w * wv.x; acc[3][1] += xv.w * wv.y; acc[3][2] += xv.w * wv.z; acc[3][3] += xv.w * wv.w;
        }
        __syncthreads();
    }

    float4 bv = *(const float4*)(B + h * HID + dg * 4);
    #pragma unroll
    for (int ii = 0; ii < 4; ii++) {
        float4 r;
        r.x = acc[ii][0] + bv.x;
        r.y = acc[ii][1] + bv.y;
        r.z = acc[ii][2] + bv.z;
        r.w = acc[ii][3] + bv.w;
        *(float4*)(Y + ((size_t)h * NNODES + i0 + ig * 4 + ii) * HID + dg * 4) = r;
    }
}

// ---------------- src/dst projections ----------------------------------------
__global__ void srcdst_kernel(const float* __restrict__ wh,
                              const float* __restrict__ asrc,
                              const float* __restrict__ adst,
                              float* __restrict__ osrc,
                              float* __restrict__ odst,
                              int total)
{
    int gw = (blockIdx.x * blockDim.x + threadIdx.x) >> 5;
    int lane = threadIdx.x & 31;
    if (gw >= total) return;
    int h = gw >> 12;
    const float* row = wh + (size_t)gw * HID;
    float v0 = row[lane], v1 = row[lane + 32];
    float s = v0 * asrc[h * HID + lane] + v1 * asrc[h * HID + lane + 32];
    float d = v0 * adst[h * HID + lane] + v1 * adst[h * HID + lane + 32];
    #pragma unroll
    for (int o = 16; o > 0; o >>= 1) {
        s += __shfl_xor_sync(0xffffffffu, s, o);
        d += __shfl_xor_sync(0xffffffffu, d, o);
    }
    if (lane == 0) { osrc[gw] = s; odst[gw] = d; }
}

// ---------------- fused attention via mma.sync m16n8k8 tf32 -------------------
// grid: (N/128, H, jsplit), block 256 (8 warps). Warp w owns i-rows i0+16w..+15.
// A (scores) generated DIRECTLY in mma fragment registers; B (wh chunk) staged
// in SMEM pre-swizzled to fragment layout as tf32, double-buffered.
__global__ void __launch_bounds__(256) attn_mma_kernel(
    const float* __restrict__ wh,    // [H][N][64]
    const float* __restrict__ ssrc,  // [H][N]
    const float* __restrict__ sdst,  // [H][N]
    const float* __restrict__ ab,    // [H]
    const int*  __restrict__ adj,    // [N][N]
    float* __restrict__ out,         // final (jsplit==1)
    int outStride,
    float* __restrict__ pnum,        // partials (jsplit>1)
    float* __restrict__ pden)
{
    __shared__ uint2 bfrag[2][1024];   // [buf][ntile*128 + kstep*32 + lane] = (b0,b1) tf32

    const int h    = blockIdx.y;
    const int t    = threadIdx.x;
    const int lane = t & 31;
    const int warp = t >> 5;
    const int gid  = lane >> 2;        // groupID
    const int tig  = lane & 3;         // thread-in-group
    const int i0   = blockIdx.x * 128;
    const int jsplit  = gridDim.z;
    const int z       = blockIdx.z;
    const int nchunks = 128 / jsplit;
    const int jc0     = z * nchunks * 32;

    const float* whh  = wh   + (size_t)h * NNODES * HID;
    const float* dstp = sdst + (size_t)h * NNODES;
    const float  bias = ab[h];

    const int iA = i0 + warp * 16 + gid;
    const int iB = iA + 8;
    const float srcA = ssrc[h * NNODES + iA] + bias;
    const float srcB = ssrc[h * NNODES + iB] + bias;
    const int* adjA = adj + (size_t)iA * NNODES;
    const int* adjB = adj + (size_t)iB * NNODES;

    float acc[8][4];
    #pragma unroll
    for (int n = 0; n < 8; n++)
        #pragma unroll
        for (int r = 0; r < 4; r++) acc[n][r] = 0.f;
    float denA = 0.f, denB = 0.f;

    // B stager: thread handles 4 float2 frag slots per chunk (coalesced STS.64)
    auto stageB = [&](uint2* buf, int jc) {
        #pragma unroll
        for (int u = 0; u < 4; u++) {
            int pos = t + 256 * u;             // = ntile*128 + ks*32 + ln
            int ln  = pos & 31;
            int ks  = (pos >> 5) & 3;
            int nt  = pos >> 7;
            int j   = jc + ks * 8 + (ln & 3);
            int d   = nt * 8 + (ln >> 2);
            uint2 v;
            v.x = cvt_tf32(whh[(size_t)j * HID + d]);
            v.y = cvt_tf32(whh[(size_t)(j + 4) * HID + d]);
            buf[pos] = v;
        }
    };

    stageB(bfrag[0], jc0);
    __syncthreads();

    for (int chunk = 0; chunk < nchunks; chunk++) {
        const int jc = jc0 + chunk * 32;
        if (chunk + 1 < nchunks) stageB(bfrag[(chunk + 1) & 1], jc + 32);
        const uint2* bb = bfrag[chunk & 1];

        #pragma unroll
        for (int ks = 0; ks < 4; ks++) {
            const int j0 = jc + ks * 8 + tig;
            const int j1 = j0 + 4;
            float d0 = dstp[j0];
            float d1 = dstp[j1];
            int m00 = adjA[j0], m10 = adjB[j0], m01 = adjA[j1], m11 = adjB[j1];

            float s00 = srcA + d0, s10 = srcB + d0, s01 = srcA + d1, s11 = srcB + d1;
            s00 = fmaxf(s00, 0.2f * s00);
            s10 = fmaxf(s10, 0.2f * s10);
            s01 = fmaxf(s01, 0.2f * s01);
            s11 = fmaxf(s11, 0.2f * s11);
            float e00 = (m00 > 0) ? __expf(s00) : 0.f;
            float e10 = (m10 > 0) ? __expf(s10) : 0.f;
            float e01 = (m01 > 0) ? __expf(s01) : 0.f;
            float e11 = (m11 > 0) ? __expf(s11) : 0.f;
            denA += e00 + e01;
            denB += e10 + e11;

            uint32_t a0 = cvt_tf32(e00);   // (row gid,   col tig)
            uint32_t a1 = cvt_tf32(e10);   // (row gid+8, col tig)
            uint32_t a2 = cvt_tf32(e01);   // (row gid,   col tig+4)
            uint32_t a3 = cvt_tf32(e11);   // (row gid+8, col tig+4)

            const uint2* bk = bb + ks * 32 + lane;
            #pragma unroll
            for (int nt = 0; nt < 8; nt++) {
                uint2 b = bk[nt * 128];
                mma1688(acc[nt], a0, a1, a2, a3, b.x, b.y);
            }
        }
        __syncthreads();
    }

    // softmax denominators: quad reduce (lanes tig=0..3 of each group)
    denA += __shfl_xor_sync(0xffffffffu, denA, 1);
    denA += __shfl_xor_sync(0xffffffffu, denA, 2);
    denB += __shfl_xor_sync(0xffffffffu, denB, 1);
    denB += __shfl_xor_sync(0xffffffffu, denB, 2);

    if (jsplit == 1) {
        const float invA = 1.f / denA;
        const float invB = 1.f / denB;
        float* oA = out + (size_t)iA * outStride + h * 64 + 2 * tig;
        float* oB = out + (size_t)iB * outStride + h * 64 + 2 * tig;
        #pragma unroll
        for (int nt = 0; nt < 8; nt++) {
            float xa0 = acc[nt][0] * invA, xa1 = acc[nt][1] * invA;
            float xb0 = acc[nt][2] * invB, xb1 = acc[nt][3] * invB;
            float2 va, vb;
            va.x = (xa0 > 0.f) ? xa0 : expm1f(xa0);
            va.y = (xa1 > 0.f) ? xa1 : expm1f(xa1);
            vb.x = (xb0 > 0.f) ? xb0 : expm1f(xb0);
            vb.y = (xb1 > 0.f) ? xb1 : expm1f(xb1);
            *(float2*)(oA + nt * 8) = va;
            *(float2*)(oB + nt * 8) = vb;
        }
    } else {
        float* pA = pnum + ((size_t)z * NNODES + iA) * HID + 2 * tig;
        float* pB = pnum + ((size_t)z * NNODES + iB) * HID + 2 * tig;
        #pragma unroll
        for (int nt = 0; nt < 8; nt++) {
            float2 va, vb;
            va.x = acc[nt][0]; va.y = acc[nt][1];
            vb.x = acc[nt][2]; vb.y = acc[nt][3];
            *(float2*)(pA + nt * 8) = va;
            *(float2*)(pB + nt * 8) = vb;
        }
        if (tig == 0) {
            pden[(size_t)z * NNODES + iA] = denA;
            pden[(size_t)z * NNODES + iB] = denB;
        }
    }
}

// ---------------- layer2 partial reduce ---------------------------------------
__global__ void reduce_kernel(const float* __restrict__ pnum,
                              const float* __restrict__ pden,
                              float* __restrict__ out)
{
    int idx = blockIdx.x * blockDim.x + threadIdx.x;   // 4096*16
    int i = idx >> 4;
    int c = (idx & 15) << 2;
    float den = pden[i] + pden[NNODES + i] + pden[2 * NNODES + i] + pden[3 * NNODES + i];
    float4 a = *(const float4*)(pnum + (size_t)i * HID + c);
    #pragma unroll
    for (int zz = 1; zz < 4; zz++) {
        float4 b = *(const float4*)(pnum + ((size_t)zz * NNODES + i) * HID + c);
        a.x += b.x; a.y += b.y; a.z += b.z; a.w += b.w;
    }
    float inv = 1.f / den;
    float v[4] = {a.x * inv, a.y * inv, a.z * inv, a.w * inv};
    #pragma unroll
    for (int r = 0; r < 4; r++) v[r] = (v[r] > 0.f) ? v[r] : expm1f(v[r]);
    float4 o4; o4.x = v[0]; o4.y = v[1]; o4.z = v[2]; o4.w = v[3];
    *(float4*)(out + (size_t)i * HID + c) = o4;
}

// ---------------- launch ------------------------------------------------------
extern "C" void kernel_launch(void* const* d_in, const int* in_sizes, int n_in,
                              void* d_out, int out_size)
{
    const float* h      = (const float*)d_in[0];
    const int*   adj    = (const int*)  d_in[1];
    const float* Wh     = (const float*)d_in[2];
    const float* bWh    = (const float*)d_in[3];
    const float* a_src  = (const float*)d_in[4];
    const float* a_dst  = (const float*)d_in[5];
    const float* a_b    = (const float*)d_in[6];
    const float* Wo     = (const float*)d_in[7];
    const float* bWo    = (const float*)d_in[8];
    const float* ao_src = (const float*)d_in[9];
    const float* ao_dst = (const float*)d_in[10];
    const float* ao_b   = (const float*)d_in[11];
    float* out = (float*)d_out;

    float *wh1, *src1, *dst1, *x2, *wh2, *src2, *dst2, *pnum, *pden;
    cudaGetSymbolAddress((void**)&wh1,  g_wh1);
    cudaGetSymbolAddress((void**)&src1, g_src1);
    cudaGetSymbolAddress((void**)&dst1, g_dst1);
    cudaGetSymbolAddress((void**)&x2,   g_x2);
    cudaGetSymbolAddress((void**)&wh2,  g_wh2);
    cudaGetSymbolAddress((void**)&src2, g_src2);
    cudaGetSymbolAddress((void**)&dst2, g_dst2);
    cudaGetSymbolAddress((void**)&pnum, g_pnum);
    cudaGetSymbolAddress((void**)&pden, g_pden);

    // Layer 1
    gemm_bias_kernel<<<dim3(NNODES / 64, 4), 256>>>(h, Wh, bWh, wh1);
    srcdst_kernel<<<4 * 512, 256>>>(wh1, a_src, a_dst, src1, dst1, 4 * NNODES);
    attn_mma_kernel<<<dim3(NNODES / 128, 4, 1), 256>>>(wh1, src1, dst1, a_b, adj, x2, 256, nullptr, nullptr);

    // Layer 2 (j-split x4, then reduce)
    gemm_bias_kernel<<<dim3(NNODES / 64, 1), 256>>>(x2, Wo, bWo, wh2);
    srcdst_kernel<<<512, 256>>>(wh2, ao_src, ao_dst, src2, dst2, NNODES);
    attn_mma_kernel<<<dim3(NNODES / 128, 1, 4), 256>>>(wh2, src2, dst2, ao_b, adj, nullptr, 64, pnum, pden);
    reduce_kernel<<<(NNODES * 16) / 256, 256>>>(pnum, pden, out);
}

// round 4
// speedup vs baseline: 5.3457x; 3.3797x over previous
#include <cuda_runtime.h>
#include <cstdint>
#include <cstddef>

#define NNODES 4096
#define INDIM 256
#define HID 64
#define LOG2E 1.4426950408889634f

// ---------------- scratch (no allocation allowed) ----------------
__device__ float g_wh1[4 * NNODES * HID];     // [H][N][64]
__device__ float g_whT1[4 * HID * NNODES];    // [H][64][N]
__device__ float g_src1[4 * NNODES];
__device__ float g_dst1[4 * NNODES];
__device__ float g_x2[NNODES * 256];          // concat heads [N][256]
__device__ float g_wh2[NNODES * HID];
__device__ float g_whT2[HID * NNODES];
__device__ float g_src2[NNODES];
__device__ float g_dst2[NNODES];
__device__ float g_pnum[2 * NNODES * 256];    // j-split partial numerators (max 8MB)
__device__ float g_pden[8 * NNODES];          // [z][H][N] partial denominators
__device__ uint32_t g_mask[NNODES * 128];     // adjacency bitmask

// ---------------- helpers ------------------------------------------------------
__device__ __forceinline__ float ex2f(float x) {
    float r; asm("ex2.approx.f32 %0, %1;" : "=f"(r) : "f"(x)); return r;
}
__device__ __forceinline__ uint32_t pack_bf16x2(float lo, float hi) {
    uint32_t r; asm("cvt.rn.bf16x2.f32 %0, %1, %2;" : "=r"(r) : "f"(hi), "f"(lo)); return r;
}
__device__ __forceinline__ void mma_bf16(float* c,
                                         uint32_t a0, uint32_t a1, uint32_t a2, uint32_t a3,
                                         uint32_t b0, uint32_t b1) {
    asm volatile(
        "mma.sync.aligned.m16n8k16.row.col.f32.bf16.bf16.f32 "
        "{%0,%1,%2,%3}, {%4,%5,%6,%7}, {%8,%9}, {%0,%1,%2,%3};"
        : "+f"(c[0]), "+f"(c[1]), "+f"(c[2]), "+f"(c[3])
        : "r"(a0), "r"(a1), "r"(a2), "r"(a3), "r"(b0), "r"(b1));
}
__device__ __forceinline__ void cp16(void* dst, const void* src) {
    uint32_t d = (uint32_t)__cvta_generic_to_shared(dst);
    asm volatile("cp.async.cg.shared.global [%0], [%1], 16;" :: "r"(d), "l"(src));
}
#define CP_COMMIT() asm volatile("cp.async.commit_group;" ::: "memory")
#define CP_WAIT(n)  asm volatile("cp.async.wait_group %0;" :: "n"(n) : "memory")

// ---------------- adjacency -> bitmask ----------------------------------------
// warp per row; grid 512 x 256 threads
__global__ void pack_adj_kernel(const int* __restrict__ adj, uint32_t* __restrict__ maskb)
{
    const int warp = threadIdx.x >> 5, lane = threadIdx.x & 31;
    const int r = blockIdx.x * 8 + warp;
    const int* row = adj + (size_t)r * NNODES;
    #pragma unroll
    for (int wg = 0; wg < 4; wg++) {
        uint32_t kept = 0;
        #pragma unroll
        for (int ww = 0; ww < 32; ww++) {
            int v = row[(wg * 32 + ww) * 32 + lane];
            uint32_t b = __ballot_sync(0xffffffffu, v > 0);
            if (lane == ww) kept = b;
        }
        maskb[(size_t)r * 128 + wg * 32 + lane] = kept;
    }
}

// ---------------- GEMM (cp.async double-buffered): Y = X@W + B; also Y^T ------
__global__ void __launch_bounds__(256) gemm_bias_kernel(
    const float* __restrict__ X, const float* __restrict__ W,
    const float* __restrict__ B, float* __restrict__ Y, float* __restrict__ YT)
{
    const int h  = blockIdx.y;
    const int i0 = blockIdx.x * 64;
    const int t  = threadIdx.x;
    const int dg = t & 15;
    const int ig = t >> 4;

    __shared__ float Xs[2][64][16];
    __shared__ float Ws[2][16][64];

    const float* Wh = W + (size_t)h * INDIM * HID;
    const int xrow = t >> 2, xseg = t & 3;
    const int wrow = t >> 4, wseg = t & 15;

    auto stage = [&](int buf, int kc) {
        cp16(&Xs[buf][xrow][xseg * 4], X + (size_t)(i0 + xrow) * INDIM + kc + xseg * 4);
        cp16(&Ws[buf][wrow][wseg * 4], Wh + (size_t)(kc + wrow) * HID + wseg * 4);
    };

    stage(0, 0);
    CP_COMMIT();

    float acc[4][4] = {};
    for (int kk = 0; kk < INDIM / 16; kk++) {
        if (kk + 1 < INDIM / 16) {
            stage((kk + 1) & 1, (kk + 1) * 16);
            CP_COMMIT();
            CP_WAIT(1);
        } else {
            CP_WAIT(0);
        }
        __syncthreads();
        const int buf = kk & 1;
        #pragma unroll
        for (int k = 0; k < 16; k++) {
            float4 wv = *(const float4*)(&Ws[buf][k][dg * 4]);
            float x0 = Xs[buf][ig * 4 + 0][k];
            float x1 = Xs[buf][ig * 4 + 1][k];
            float x2 = Xs[buf][ig * 4 + 2][k];
            float x3 = Xs[buf][ig * 4 + 3][k];
            acc[0][0] += x0 * wv.x; acc[0][1] += x0 * wv.y; acc[0][2] += x0 * wv.z; acc[0][3] += x0 * wv.w;
            acc[1][0] += x1 * wv.x; acc[1][1] += x1 * wv.y; acc[1][2] += x1 * wv.z; acc[1][3] += x1 * wv.w;
            acc[2][0] += x2 * wv.x; acc[2][1] += x2 * wv.y; acc[2][2] += x2 * wv.z; acc[2][3] += x2 * wv.w;
            acc[3][0] += x3 * wv.x; acc[3][1] += x3 * wv.y; acc[3][2] += x3 * wv.z; acc[3][3] += x3 * wv.w;
        }
        __syncthreads();
    }

    float4 bv = *(const float4*)(B + h * HID + dg * 4);
    float bb[4] = {bv.x, bv.y, bv.z, bv.w};
    #pragma unroll
    for (int ii = 0; ii < 4; ii++) {
        float4 r;
        r.x = acc[ii][0] + bb[0];
        r.y = acc[ii][1] + bb[1];
        r.z = acc[ii][2] + bb[2];
        r.w = acc[ii][3] + bb[3];
        *(float4*)(Y + ((size_t)h * NNODES + i0 + ig * 4 + ii) * HID + dg * 4) = r;
    }
    #pragma unroll
    for (int c = 0; c < 4; c++) {
        float4 r;
        r.x = acc[0][c] + bb[c];
        r.y = acc[1][c] + bb[c];
        r.z = acc[2][c] + bb[c];
        r.w = acc[3][c] + bb[c];
        *(float4*)(YT + ((size_t)h * HID + dg * 4 + c) * NNODES + i0 + ig * 4) = r;
    }
}

// ---------------- src/dst projections (scaled by log2e, bias folded) ----------
__global__ void srcdst_kernel(const float* __restrict__ wh,
                              const float* __restrict__ asrc,
                              const float* __restrict__ adst,
                              const float* __restrict__ ab,
                              float* __restrict__ osrc,
                              float* __restrict__ odst,
                              int total)
{
    int gw = (blockIdx.x * blockDim.x + threadIdx.x) >> 5;
    int lane = threadIdx.x & 31;
    if (gw >= total) return;
    int h = gw >> 12;
    const float* row = wh + (size_t)gw * HID;
    float v0 = row[lane], v1 = row[lane + 32];
    float s = v0 * asrc[h * HID + lane] + v1 * asrc[h * HID + lane + 32];
    float d = v0 * adst[h * HID + lane] + v1 * adst[h * HID + lane + 32];
    #pragma unroll
    for (int o = 16; o > 0; o >>= 1) {
        s += __shfl_xor_sync(0xffffffffu, s, o);
        d += __shfl_xor_sync(0xffffffffu, d, o);
    }
    if (lane == 0) {
        osrc[gw] = (s + ab[h]) * LOG2E;
        odst[gw] = d * LOG2E;
    }
}

// ---------------- fused attention via mma.sync m16n8k16 bf16 ------------------
// grid: (N/128, H, jsplit), block 256 (8 warps). Warp w owns i-rows i0+16w..+15.
// Always writes partials (pnum/pden); reduce kernel finishes softmax + elu.
__global__ void __launch_bounds__(256, 2) attn_mma_kernel(
    const float* __restrict__ whT,    // [H][64][N]
    const float* __restrict__ srcL,   // [H][N]  (scaled, biased)
    const float* __restrict__ dstL,   // [H][N]  (scaled)
    const uint32_t* __restrict__ maskb, // [N][128]
    float* __restrict__ pnum,         // [z][N][pcols]
    float* __restrict__ pden,         // [z][H][N]
    int pcols, int nheads)
{
    __shared__ uint2 bfrag[2][2][8][32];  // [buf][ks][nt][lane] = (b0,b1)

    const int h    = blockIdx.y;
    const int t    = threadIdx.x;
    const int lane = t & 31;
    const int warp = t >> 5;
    const int gid  = lane >> 2;
    const int tig  = lane & 3;
    const int i0   = blockIdx.x * 128;
    const int z       = blockIdx.z;
    const int jsplit  = gridDim.z;
    const int nchunks = (NNODES / 32) / jsplit;
    const int jc0     = z * nchunks * 32;

    const int hN = h * NNODES;
    const int iA = i0 + warp * 16 + gid;
    const int iB = iA + 8;
    const float srcA = srcL[hN + iA];
    const float srcB = srcL[hN + iB];
    const float* dstp = dstL + hN;
    const uint32_t* mApt = maskb + (size_t)iA * 128 + (jc0 >> 5);
    const uint32_t* mBpt = maskb + (size_t)iB * 128 + (jc0 >> 5);

    // staging mapping: thread covers rows d = sd and sd+32, local j = 4*e8..+3
    const int sd = t >> 3;
    const int e8 = t & 7;
    const int sks   = e8 >> 2;
    const int shalf = (e8 >> 1) & 1;
    const int smb   = 2 * (e8 & 1);
    const float* whh = whT + (size_t)h * HID * NNODES;

    const uint32_t m0 = 1u   << (2 * tig);
    const uint32_t m1 = 2u   << (2 * tig);
    const uint32_t m8 = 256u << (2 * tig);
    const uint32_t m9 = 512u << (2 * tig);

    float acc[8][4];
    #pragma unroll
    for (int n = 0; n < 8; n++)
        #pragma unroll
        for (int r = 0; r < 4; r++) acc[n][r] = 0.f;
    float denA = 0.f, denB = 0.f;

    // stage chunk 0
    {
        const float* p = whh + (size_t)sd * NNODES + jc0 + 4 * e8;
        float4 v0 = *(const float4*)p;
        float4 v1 = *(const float4*)(p + (size_t)32 * NNODES);
        uint32_t* s0 = (uint32_t*)&bfrag[0][sks][sd >> 3][(sd & 7) * 4 + smb];
        s0[shalf]     = pack_bf16x2(v0.x, v0.y);
        s0[2 + shalf] = pack_bf16x2(v0.z, v0.w);
        uint32_t* s1 = (uint32_t*)&bfrag[0][sks][(sd + 32) >> 3][((sd + 32) & 7) * 4 + smb];
        s1[shalf]     = pack_bf16x2(v1.x, v1.y);
        s1[2 + shalf] = pack_bf16x2(v1.z, v1.w);
    }
    __syncthreads();

    for (int cg = 0; cg < nchunks; cg += 4) {
        uint4 wA4 = *(const uint4*)mApt; mApt += 4;
        uint4 wB4 = *(const uint4*)mBpt; mBpt += 4;
        #pragma unroll
        for (int cc = 0; cc < 4; cc++) {
            const int chunk = cg + cc;
            const int jc = jc0 + chunk * 32;
            const uint32_t wAw = (cc == 0) ? wA4.x : (cc == 1) ? wA4.y : (cc == 2) ? wA4.z : wA4.w;
            const uint32_t wBw = (cc == 0) ? wB4.x : (cc == 1) ? wB4.y : (cc == 2) ? wB4.z : wB4.w;
            const bool hasNext = (chunk + 1 < nchunks);

            // prefetch next B-chunk (gmem)
            float4 sv0, sv1;
            if (hasNext) {
                const float* p = whh + (size_t)sd * NNODES + jc + 32 + 4 * e8;
                sv0 = *(const float4*)p;
                sv1 = *(const float4*)(p + (size_t)32 * NNODES);
            }

            float dstv = dstp[jc + lane];
            uint32_t aA[2][2], aB[2][2];
            #pragma unroll
            for (int ks = 0; ks < 2; ks++) {
                const uint32_t wa = ks ? (wAw >> 16) : wAw;
                const uint32_t wb = ks ? (wBw >> 16) : wBw;
                const int base = ks * 16 + 2 * tig;
                float d0 = __shfl_sync(0xffffffffu, dstv, base);
                float d1 = __shfl_sync(0xffffffffu, dstv, base + 1);
                float d8 = __shfl_sync(0xffffffffu, dstv, base + 8);
                float d9 = __shfl_sync(0xffffffffu, dstv, base + 9);

                float sA0 = srcA + d0, sA1 = srcA + d1, sA8 = srcA + d8, sA9 = srcA + d9;
                float sB0 = srcB + d0, sB1 = srcB + d1, sB8 = srcB + d8, sB9 = srcB + d9;
                sA0 = fmaxf(sA0, 0.2f * sA0); sA1 = fmaxf(sA1, 0.2f * sA1);
                sA8 = fmaxf(sA8, 0.2f * sA8); sA9 = fmaxf(sA9, 0.2f * sA9);
                sB0 = fmaxf(sB0, 0.2f * sB0); sB1 = fmaxf(sB1, 0.2f * sB1);
                sB8 = fmaxf(sB8, 0.2f * sB8); sB9 = fmaxf(sB9, 0.2f * sB9);
                float eA0 = (wa & m0) ? ex2f(sA0) : 0.f;
                float eA1 = (wa & m1) ? ex2f(sA1) : 0.f;
                float eA8 = (wa & m8) ? ex2f(sA8) : 0.f;
                float eA9 = (wa & m9) ? ex2f(sA9) : 0.f;
                float eB0 = (wb & m0) ? ex2f(sB0) : 0.f;
                float eB1 = (wb & m1) ? ex2f(sB1) : 0.f;
                float eB8 = (wb & m8) ? ex2f(sB8) : 0.f;
                float eB9 = (wb & m9) ? ex2f(sB9) : 0.f;
                denA += (eA0 + eA1) + (eA8 + eA9);
                denB += (eB0 + eB1) + (eB8 + eB9);
                aA[ks][0] = pack_bf16x2(eA0, eA1);
                aA[ks][1] = pack_bf16x2(eA8, eA9);
                aB[ks][0] = pack_bf16x2(eB0, eB1);
                aB[ks][1] = pack_bf16x2(eB8, eB9);
            }

            // store next B-chunk fragments
            if (hasNext) {
                const int nbuf = (chunk + 1) & 1;
                uint32_t* s0 = (uint32_t*)&bfrag[nbuf][sks][sd >> 3][(sd & 7) * 4 + smb];
                s0[shalf]     = pack_bf16x2(sv0.x, sv0.y);
                s0[2 + shalf] = pack_bf16x2(sv0.z, sv0.w);
                uint32_t* s1 = (uint32_t*)&bfrag[nbuf][sks][(sd + 32) >> 3][((sd + 32) & 7) * 4 + smb];
                s1[shalf]     = pack_bf16x2(sv1.x, sv1.y);
                s1[2 + shalf] = pack_bf16x2(sv1.z, sv1.w);
            }

            // MMA over current chunk
            const int buf = chunk & 1;
            #pragma unroll
            for (int ks = 0; ks < 2; ks++) {
                const uint2* bk = &bfrag[buf][ks][0][lane];
                #pragma unroll
                for (int nt = 0; nt < 8; nt++) {
                    uint2 b = bk[nt * 32];
                    mma_bf16(acc[nt], aA[ks][0], aB[ks][0], aA[ks][1], aB[ks][1], b.x, b.y);
                }
            }
            __syncthreads();
        }
    }

    denA += __shfl_xor_sync(0xffffffffu, denA, 1);
    denA += __shfl_xor_sync(0xffffffffu, denA, 2);
    denB += __shfl_xor_sync(0xffffffffu, denB, 1);
    denB += __shfl_xor_sync(0xffffffffu, denB, 2);

    float* pA = pnum + ((size_t)z * NNODES + iA) * pcols + h * 64 + 2 * tig;
    float* pB = pnum + ((size_t)z * NNODES + iB) * pcols + h * 64 + 2 * tig;
    #pragma unroll
    for (int nt = 0; nt < 8; nt++) {
        float2 va, vb;
        va.x = acc[nt][0]; va.y = acc[nt][1];
        vb.x = acc[nt][2]; vb.y = acc[nt][3];
        *(float2*)(pA + nt * 8) = va;
        *(float2*)(pB + nt * 8) = vb;
    }
    if (tig == 0) {
        pden[((size_t)z * nheads + h) * NNODES + iA] = denA;
        pden[((size_t)z * nheads + h) * NNODES + iB] = denB;
    }
}

// ---------------- partial reduce + softmax divide + elu -----------------------
__global__ void reduce_kernel(const float* __restrict__ pnum,
                              const float* __restrict__ pden,
                              float* __restrict__ out,
                              int zn, int cols, int cqs, int H)
{
    int idx = blockIdx.x * blockDim.x + threadIdx.x;
    int i = idx >> cqs;
    int c = (idx & ((1 << cqs) - 1)) << 2;
    int h = c >> 6;
    float den = 0.f;
    for (int zz = 0; zz < zn; zz++)
        den += pden[((size_t)zz * H + h) * NNODES + i];
    float4 a = *(const float4*)(pnum + ((size_t)i) * cols + c);
    for (int zz = 1; zz < zn; zz++) {
        float4 b = *(const float4*)(pnum + ((size_t)zz * NNODES + i) * cols + c);
        a.x += b.x; a.y += b.y; a.z += b.z; a.w += b.w;
    }
    float inv = 1.f / den;
    float v[4] = {a.x * inv, a.y * inv, a.z * inv, a.w * inv};
    #pragma unroll
    for (int r = 0; r < 4; r++) v[r] = (v[r] > 0.f) ? v[r] : expm1f(v[r]);
    float4 o4; o4.x = v[0]; o4.y = v[1]; o4.z = v[2]; o4.w = v[3];
    *(float4*)(out + (size_t)i * cols + c) = o4;
}

// ---------------- launch ------------------------------------------------------
extern "C" void kernel_launch(void* const* d_in, const int* in_sizes, int n_in,
                              void* d_out, int out_size)
{
    const float* h      = (const float*)d_in[0];
    const int*   adj    = (const int*)  d_in[1];
    const float* Wh     = (const float*)d_in[2];
    const float* bWh    = (const float*)d_in[3];
    const float* a_src  = (const float*)d_in[4];
    const float* a_dst  = (const float*)d_in[5];
    const float* a_b    = (const float*)d_in[6];
    const float* Wo     = (const float*)d_in[7];
    const float* bWo    = (const float*)d_in[8];
    const float* ao_src = (const float*)d_in[9];
    const float* ao_dst = (const float*)d_in[10];
    const float* ao_b   = (const float*)d_in[11];
    float* out = (float*)d_out;

    float *wh1, *whT1, *src1, *dst1, *x2, *wh2, *whT2, *src2, *dst2, *pnum, *pden;
    uint32_t* maskb;
    cudaGetSymbolAddress((void**)&wh1,  g_wh1);
    cudaGetSymbolAddress((void**)&whT1, g_whT1);
    cudaGetSymbolAddress((void**)&src1, g_src1);
    cudaGetSymbolAddress((void**)&dst1, g_dst1);
    cudaGetSymbolAddress((void**)&x2,   g_x2);
    cudaGetSymbolAddress((void**)&wh2,  g_wh2);
    cudaGetSymbolAddress((void**)&whT2, g_whT2);
    cudaGetSymbolAddress((void**)&src2, g_src2);
    cudaGetSymbolAddress((void**)&dst2, g_dst2);
    cudaGetSymbolAddress((void**)&pnum, g_pnum);
    cudaGetSymbolAddress((void**)&pden, g_pden);
    cudaGetSymbolAddress((void**)&maskb, g_mask);

    pack_adj_kernel<<<NNODES / 8, 256>>>(adj, maskb);

    // Layer 1 (jsplit=2)
    gemm_bias_kernel<<<dim3(NNODES / 64, 4), 256>>>(h, Wh, bWh, wh1, whT1);
    srcdst_kernel<<<4 * 512, 256>>>(wh1, a_src, a_dst, a_b, src1, dst1, 4 * NNODES);
    attn_mma_kernel<<<dim3(NNODES / 128, 4, 2), 256>>>(whT1, src1, dst1, maskb, pnum, pden, 256, 4);
    reduce_kernel<<<(NNODES * 64) / 256, 256>>>(pnum, pden, x2, 2, 256, 6, 4);

    // Layer 2 (jsplit=4)
    gemm_bias_kernel<<<dim3(NNODES / 64, 1), 256>>>(x2, Wo, bWo, wh2, whT2);
    srcdst_kernel<<<512, 256>>>(wh2, ao_src, ao_dst, ao_b, src2, dst2, NNODES);
    attn_mma_kernel<<<dim3(NNODES / 128, 1, 4), 256>>>(whT2, src2, dst2, maskb, pnum, pden, 64, 1);
    reduce_kernel<<<(NNODES * 16) / 256, 256>>>(pnum, pden, out, 4, 64, 4, 1);
}

// round 5
// speedup vs baseline: 6.3291x; 1.1840x over previous
#include <cuda_runtime.h>
#include <cstdint>
#include <cstddef>

#define NNODES 4096
#define INDIM 256
#define HID 64
#define LOG2E 1.4426950408889634f

// ---------------- scratch (no allocation allowed) ----------------
__device__ float g_wh1[4 * NNODES * HID];     // [H][N][64] fp32 (for srcdst)
__device__ float g_x2[NNODES * 256];          // concat heads [N][256]
__device__ float g_wh2[NNODES * HID];
__device__ float g_src1[4 * NNODES];
__device__ float g_dst1[4 * NNODES];
__device__ float g_src2[NNODES];
__device__ float g_dst2[NNODES];
__device__ float g_pnum[2 * NNODES * 256];    // partial numerators (8MB max)
__device__ float g_pden[8 * NNODES];          // [z][H][N] partial denominators
__device__ uint32_t g_mask[NNODES * 128];     // adjacency bitmask
__device__ uint4 g_whF1[4 * 128 * 256];       // bf16 frag tensor L1: [H][chunk][2][8][32] uint2
__device__ uint4 g_whF2[128 * 256];           // bf16 frag tensor L2

// ---------------- helpers ------------------------------------------------------
__device__ __forceinline__ float ex2f(float x) {
    float r; asm("ex2.approx.f32 %0, %1;" : "=f"(r) : "f"(x)); return r;
}
__device__ __forceinline__ uint32_t pack_bf16x2(float lo, float hi) {
    uint32_t r; asm("cvt.rn.bf16x2.f32 %0, %1, %2;" : "=r"(r) : "f"(hi), "f"(lo)); return r;
}
__device__ __forceinline__ void mma_bf16(float* c,
                                         uint32_t a0, uint32_t a1, uint32_t a2, uint32_t a3,
                                         uint32_t b0, uint32_t b1) {
    asm volatile(
        "mma.sync.aligned.m16n8k16.row.col.f32.bf16.bf16.f32 "
        "{%0,%1,%2,%3}, {%4,%5,%6,%7}, {%8,%9}, {%0,%1,%2,%3};"
        : "+f"(c[0]), "+f"(c[1]), "+f"(c[2]), "+f"(c[3])
        : "r"(a0), "r"(a1), "r"(a2), "r"(a3), "r"(b0), "r"(b1));
}
__device__ __forceinline__ void cp16(void* dst, const void* src) {
    uint32_t d = (uint32_t)__cvta_generic_to_shared(dst);
    asm volatile("cp.async.cg.shared.global [%0], [%1], 16;" :: "r"(d), "l"(src));
}
#define CP_COMMIT() asm volatile("cp.async.commit_group;" ::: "memory")
#define CP_WAIT(n)  asm volatile("cp.async.wait_group %0;" :: "n"(n) : "memory")

// ---------------- adjacency -> bitmask ----------------------------------------
__global__ void pack_adj_kernel(const int* __restrict__ adj, uint32_t* __restrict__ maskb)
{
    const int warp = threadIdx.x >> 5, lane = threadIdx.x & 31;
    const int r = blockIdx.x * 8 + warp;
    const int* row = adj + (size_t)r * NNODES;
    #pragma unroll
    for (int wg = 0; wg < 4; wg++) {
        uint32_t kept = 0;
        #pragma unroll
        for (int ww = 0; ww < 32; ww++) {
            int v = row[(wg * 32 + ww) * 32 + lane];
            uint32_t b = __ballot_sync(0xffffffffu, v > 0);
            if (lane == ww) kept = b;
        }
        maskb[(size_t)r * 128 + wg * 32 + lane] = kept;
    }
}

// ---------------- GEMM: Y = X@W + B (fp32) + bf16 MMA-fragment tensor ---------
__global__ void __launch_bounds__(256) gemm_bias_kernel(
    const float* __restrict__ X, const float* __restrict__ W,
    const float* __restrict__ B, float* __restrict__ Y, uint4* __restrict__ YF)
{
    const int h  = blockIdx.y;
    const int i0 = blockIdx.x * 64;
    const int t  = threadIdx.x;
    const int dg = t & 15;
    const int ig = t >> 4;

    __shared__ float Xs[2][64][16];
    __shared__ float Ws[2][16][64];

    const float* Wh = W + (size_t)h * INDIM * HID;
    const int xrow = t >> 2, xseg = t & 3;
    const int wrow = t >> 4, wseg = t & 15;

    auto stage = [&](int buf, int kc) {
        cp16(&Xs[buf][xrow][xseg * 4], X + (size_t)(i0 + xrow) * INDIM + kc + xseg * 4);
        cp16(&Ws[buf][wrow][wseg * 4], Wh + (size_t)(kc + wrow) * HID + wseg * 4);
    };

    stage(0, 0);
    CP_COMMIT();

    float acc[4][4] = {};
    for (int kk = 0; kk < INDIM / 16; kk++) {
        if (kk + 1 < INDIM / 16) {
            stage((kk + 1) & 1, (kk + 1) * 16);
            CP_COMMIT();
            CP_WAIT(1);
        } else {
            CP_WAIT(0);
        }
        __syncthreads();
        const int buf = kk & 1;
        #pragma unroll
        for (int k = 0; k < 16; k++) {
            float4 wv = *(const float4*)(&Ws[buf][k][dg * 4]);
            float x0 = Xs[buf][ig * 4 + 0][k];
            float x1 = Xs[buf][ig * 4 + 1][k];
            float x2 = Xs[buf][ig * 4 + 2][k];
            float x3 = Xs[buf][ig * 4 + 3][k];
            acc[0][0] += x0 * wv.x; acc[0][1] += x0 * wv.y; acc[0][2] += x0 * wv.z; acc[0][3] += x0 * wv.w;
            acc[1][0] += x1 * wv.x; acc[1][1] += x1 * wv.y; acc[1][2] += x1 * wv.z; acc[1][3] += x1 * wv.w;
            acc[2][0] += x2 * wv.x; acc[2][1] += x2 * wv.y; acc[2][2] += x2 * wv.z; acc[2][3] += x2 * wv.w;
            acc[3][0] += x3 * wv.x; acc[3][1] += x3 * wv.y; acc[3][2] += x3 * wv.z; acc[3][3] += x3 * wv.w;
        }
        __syncthreads();
    }

    float4 bv = *(const float4*)(B + h * HID + dg * 4);
    float bb[4] = {bv.x, bv.y, bv.z, bv.w};
    #pragma unroll
    for (int ii = 0; ii < 4; ii++) {
        float4 r;
        r.x = acc[ii][0] + bb[0];
        r.y = acc[ii][1] + bb[1];
        r.z = acc[ii][2] + bb[2];
        r.w = acc[ii][3] + bb[3];
        *(float4*)(Y + ((size_t)h * NNODES + i0 + ig * 4 + ii) * HID + dg * 4) = r;
    }
    // bf16 fragment tensor: [h][chunk][ks][nt][lane] uint2, halves by (j%16)/8
    uint32_t* fb = (uint32_t*)(YF + (size_t)h * 128 * 256);
    #pragma unroll
    for (int c = 0; c < 4; c++) {
        const int d = dg * 4 + c;
        const int nt = d >> 3;
        const int lnb = (d & 7) * 4;
        #pragma unroll
        for (int p = 0; p < 2; p++) {
            const int jp = i0 + ig * 4 + 2 * p;      // even node index
            const int chunk = jp >> 5;
            const int ks = (jp >> 4) & 1;
            const int rr = jp & 15;
            const int lanei = lnb + ((rr & 7) >> 1);
            uint32_t val = pack_bf16x2(acc[2 * p][c] + bb[c], acc[2 * p + 1][c] + bb[c]);
            size_t idx = (((size_t)chunk * 2 + ks) * 8 + nt) * 32 + lanei;
            fb[idx * 2 + (rr >> 3)] = val;
        }
    }
}

// ---------------- src/dst projections (scaled by log2e, bias folded) ----------
__global__ void srcdst_kernel(const float* __restrict__ wh,
                              const float* __restrict__ asrc,
                              const float* __restrict__ adst,
                              const float* __restrict__ ab,
                              float* __restrict__ osrc,
                              float* __restrict__ odst,
                              int total)
{
    int gw = (blockIdx.x * blockDim.x + threadIdx.x) >> 5;
    int lane = threadIdx.x & 31;
    if (gw >= total) return;
    int h = gw >> 12;
    const float* row = wh + (size_t)gw * HID;
    float v0 = row[lane], v1 = row[lane + 32];
    float s = v0 * asrc[h * HID + lane] + v1 * asrc[h * HID + lane + 32];
    float d = v0 * adst[h * HID + lane] + v1 * adst[h * HID + lane + 32];
    #pragma unroll
    for (int o = 16; o > 0; o >>= 1) {
        s += __shfl_xor_sync(0xffffffffu, s, o);
        d += __shfl_xor_sync(0xffffffffu, d, o);
    }
    if (lane == 0) {
        osrc[gw] = (s + ab[h]) * LOG2E;
        odst[gw] = d * LOG2E;
    }
}

// ---------------- fused attention: mma m16n8k16 bf16 + cp.async B pipeline ----
__global__ void __launch_bounds__(256, 2) attn_mma_kernel(
    const uint4* __restrict__ whF,      // [H][128][2][8][32] uint2 (as uint4*)
    const float* __restrict__ srcL,     // [H][N] (scaled, biased)
    const float* __restrict__ dstL,     // [H][N] (scaled)
    const uint32_t* __restrict__ maskb, // [N][128]
    float* __restrict__ pnum,           // [z][N][pcols]
    float* __restrict__ pden,           // [z][H][N]
    int pcols, int nheads)
{
    __shared__ alignas(16) uint2 bfrag[3][2][8][32];   // 3-stage, 4KB each
    __shared__ float dsts[2048];

    const int h    = blockIdx.y;
    const int t    = threadIdx.x;
    const int lane = t & 31;
    const int warp = t >> 5;
    const int gid  = lane >> 2;
    const int tig  = lane & 3;
    const int i0   = blockIdx.x * 128;
    const int z       = blockIdx.z;
    const int jsplit  = gridDim.z;
    const int nchunks = (NNODES / 32) / jsplit;
    const int jc0     = z * nchunks * 32;

    const int hN = h * NNODES;
    // stage dst slice once
    for (int q = t; q < nchunks * 8; q += 256)
        *(float4*)(dsts + q * 4) = *(const float4*)(dstL + hN + jc0 + q * 4);

    const int iA = i0 + warp * 16 + gid;
    const int iB = iA + 8;
    const float srcA = srcL[hN + iA];
    const float srcB = srcL[hN + iB];
    const uint32_t* mApt = maskb + (size_t)iA * 128 + (jc0 >> 5);
    const uint32_t* mBpt = maskb + (size_t)iB * 128 + (jc0 >> 5);

    const uint2* gsrc = (const uint2*)whF + ((size_t)h * 128 + (jc0 >> 5)) * 512;
    uint2* sbase = &bfrag[0][0][0][0];

    const uint32_t m0 = 1u   << (2 * tig);
    const uint32_t m1 = 2u   << (2 * tig);
    const uint32_t m8 = 256u << (2 * tig);
    const uint32_t m9 = 512u << (2 * tig);

    float acc[8][4];
    #pragma unroll
    for (int n = 0; n < 8; n++)
        #pragma unroll
        for (int r = 0; r < 4; r++) acc[n][r] = 0.f;
    float denA = 0.f, denB = 0.f;

    // prologue: stage chunks 0,1
    cp16(sbase + 0 * 512 + t * 2, gsrc + 0 * 512 + t * 2);
    CP_COMMIT();
    cp16(sbase + 1 * 512 + t * 2, gsrc + 1 * 512 + t * 2);
    CP_COMMIT();

    uint4 wA4, wB4;
    int buf = 0, nbuf = 2;
    for (int chunk = 0; chunk < nchunks; chunk++) {
        if ((chunk & 3) == 0) {
            wA4 = *(const uint4*)mApt; mApt += 4;
            wB4 = *(const uint4*)mBpt; mBpt += 4;
        }
        const int cc = chunk & 3;
        const uint32_t wAw = (cc == 0) ? wA4.x : (cc == 1) ? wA4.y : (cc == 2) ? wA4.z : wA4.w;
        const uint32_t wBw = (cc == 0) ? wB4.x : (cc == 1) ? wB4.y : (cc == 2) ? wB4.z : wB4.w;

        CP_WAIT(1);
        __syncthreads();
        if (chunk + 2 < nchunks)
            cp16(sbase + nbuf * 512 + t * 2, gsrc + (size_t)(chunk + 2) * 512 + t * 2);
        CP_COMMIT();

        // A fragments: masked exp scores
        uint32_t aA[2][2], aB[2][2];
        const int jb = chunk * 32;
        #pragma unroll
        for (int ks = 0; ks < 2; ks++) {
            const float* dp = dsts + jb + ks * 16 + 2 * tig;
            float d0 = dp[0], d1 = dp[1], d8 = dp[8], d9 = dp[9];
            const uint32_t wa = ks ? (wAw >> 16) : wAw;
            const uint32_t wb = ks ? (wBw >> 16) : wBw;

            float sA0 = srcA + d0, sA1 = srcA + d1, sA8 = srcA + d8, sA9 = srcA + d9;
            float sB0 = srcB + d0, sB1 = srcB + d1, sB8 = srcB + d8, sB9 = srcB + d9;
            sA0 = fmaxf(sA0, 0.2f * sA0); sA1 = fmaxf(sA1, 0.2f * sA1);
            sA8 = fmaxf(sA8, 0.2f * sA8); sA9 = fmaxf(sA9, 0.2f * sA9);
            sB0 = fmaxf(sB0, 0.2f * sB0); sB1 = fmaxf(sB1, 0.2f * sB1);
            sB8 = fmaxf(sB8, 0.2f * sB8); sB9 = fmaxf(sB9, 0.2f * sB9);
            float eA0 = (wa & m0) ? ex2f(sA0) : 0.f;
            float eA1 = (wa & m1) ? ex2f(sA1) : 0.f;
            float eA8 = (wa & m8) ? ex2f(sA8) : 0.f;
            float eA9 = (wa & m9) ? ex2f(sA9) : 0.f;
            float eB0 = (wb & m0) ? ex2f(sB0) : 0.f;
            float eB1 = (wb & m1) ? ex2f(sB1) : 0.f;
            float eB8 = (wb & m8) ? ex2f(sB8) : 0.f;
            float eB9 = (wb & m9) ? ex2f(sB9) : 0.f;
            denA += (eA0 + eA1) + (eA8 + eA9);
            denB += (eB0 + eB1) + (eB8 + eB9);
            aA[ks][0] = pack_bf16x2(eA0, eA1);
            aA[ks][1] = pack_bf16x2(eA8, eA9);
            aB[ks][0] = pack_bf16x2(eB0, eB1);
            aB[ks][1] = pack_bf16x2(eB8, eB9);
        }

        // MMAs
        #pragma unroll
        for (int ks = 0; ks < 2; ks++) {
            const uint2* bk = &bfrag[buf][ks][0][lane];
            #pragma unroll
            for (int nt = 0; nt < 8; nt++) {
                uint2 b = bk[nt * 32];
                mma_bf16(acc[nt], aA[ks][0], aB[ks][0], aA[ks][1], aB[ks][1], b.x, b.y);
            }
        }

        buf  = (buf == 2)  ? 0 : buf + 1;
        nbuf = (nbuf == 2) ? 0 : nbuf + 1;
    }

    denA += __shfl_xor_sync(0xffffffffu, denA, 1);
    denA += __shfl_xor_sync(0xffffffffu, denA, 2);
    denB += __shfl_xor_sync(0xffffffffu, denB, 1);
    denB += __shfl_xor_sync(0xffffffffu, denB, 2);

    float* pA = pnum + ((size_t)z * NNODES + iA) * pcols + h * 64 + 2 * tig;
    float* pB = pnum + ((size_t)z * NNODES + iB) * pcols + h * 64 + 2 * tig;
    #pragma unroll
    for (int nt = 0; nt < 8; nt++) {
        float2 va, vb;
        va.x = acc[nt][0]; va.y = acc[nt][1];
        vb.x = acc[nt][2]; vb.y = acc[nt][3];
        *(float2*)(pA + nt * 8) = va;
        *(float2*)(pB + nt * 8) = vb;
    }
    if (tig == 0) {
        pden[((size_t)z * nheads + h) * NNODES + iA] = denA;
        pden[((size_t)z * nheads + h) * NNODES + iB] = denB;
    }
}

// ---------------- partial reduce + softmax divide + elu -----------------------
__global__ void reduce_kernel(const float* __restrict__ pnum,
                              const float* __restrict__ pden,
                              float* __restrict__ out,
                              int zn, int cols, int cqs, int H)
{
    int idx = blockIdx.x * blockDim.x + threadIdx.x;
    int i = idx >> cqs;
    int c = (idx & ((1 << cqs) - 1)) << 2;
    int h = c >> 6;
    float den = 0.f;
    for (int zz = 0; zz < zn; zz++)
        den += pden[((size_t)zz * H + h) * NNODES + i];
    float4 a = *(const float4*)(pnum + ((size_t)i) * cols + c);
    for (int zz = 1; zz < zn; zz++) {
        float4 b = *(const float4*)(pnum + ((size_t)zz * NNODES + i) * cols + c);
        a.x += b.x; a.y += b.y; a.z += b.z; a.w += b.w;
    }
    float inv = 1.f / den;
    float v[4] = {a.x * inv, a.y * inv, a.z * inv, a.w * inv};
    #pragma unroll
    for (int r = 0; r < 4; r++) v[r] = (v[r] > 0.f) ? v[r] : expm1f(v[r]);
    float4 o4; o4.x = v[0]; o4.y = v[1]; o4.z = v[2]; o4.w = v[3];
    *(float4*)(out + (size_t)i * cols + c) = o4;
}

// ---------------- launch ------------------------------------------------------
extern "C" void kernel_launch(void* const* d_in, const int* in_sizes, int n_in,
                              void* d_out, int out_size)
{
    const float* h      = (const float*)d_in[0];
    const int*   adj    = (const int*)  d_in[1];
    const float* Wh     = (const float*)d_in[2];
    const float* bWh    = (const float*)d_in[3];
    const float* a_src  = (const float*)d_in[4];
    const float* a_dst  = (const float*)d_in[5];
    const float* a_b    = (const float*)d_in[6];
    const float* Wo     = (const float*)d_in[7];
    const float* bWo    = (const float*)d_in[8];
    const float* ao_src = (const float*)d_in[9];
    const float* ao_dst = (const float*)d_in[10];
    const float* ao_b   = (const float*)d_in[11];
    float* out = (float*)d_out;

    float *wh1, *src1, *dst1, *x2, *wh2, *src2, *dst2, *pnum, *pden;
    uint32_t* maskb;
    uint4 *whF1, *whF2;
    cudaGetSymbolAddress((void**)&wh1,  g_wh1);
    cudaGetSymbolAddress((void**)&src1, g_src1);
    cudaGetSymbolAddress((void**)&dst1, g_dst1);
    cudaGetSymbolAddress((void**)&x2,   g_x2);
    cudaGetSymbolAddress((void**)&wh2,  g_wh2);
    cudaGetSymbolAddress((void**)&src2, g_src2);
    cudaGetSymbolAddress((void**)&dst2, g_dst2);
    cudaGetSymbolAddress((void**)&pnum, g_pnum);
    cudaGetSymbolAddress((void**)&pden, g_pden);
    cudaGetSymbolAddress((void**)&maskb, g_mask);
    cudaGetSymbolAddress((void**)&whF1, g_whF1);
    cudaGetSymbolAddress((void**)&whF2, g_whF2);

    pack_adj_kernel<<<NNODES / 8, 256>>>(adj, maskb);

    // Layer 1 (jsplit=2)
    gemm_bias_kernel<<<dim3(NNODES / 64, 4), 256>>>(h, Wh, bWh, wh1, whF1);
    srcdst_kernel<<<4 * 512, 256>>>(wh1, a_src, a_dst, a_b, src1, dst1, 4 * NNODES);
    attn_mma_kernel<<<dim3(NNODES / 128, 4, 2), 256>>>(whF1, src1, dst1, maskb, pnum, pden, 256, 4);
    reduce_kernel<<<(NNODES * 64) / 256, 256>>>(pnum, pden, x2, 2, 256, 6, 4);

    // Layer 2 (jsplit=8)
    gemm_bias_kernel<<<dim3(NNODES / 64, 1), 256>>>(x2, Wo, bWo, wh2, whF2);
    srcdst_kernel<<<512, 256>>>(wh2, ao_src, ao_dst, ao_b, src2, dst2, NNODES);
    attn_mma_kernel<<<dim3(NNODES / 128, 1, 8), 256>>>(whF2, src2, dst2, maskb, pnum, pden, 64, 1);
    reduce_kernel<<<(NNODES * 16) / 256, 256>>>(pnum, pden, out, 8, 64, 4, 1);
}

// round 7
// speedup vs baseline: 7.5909x; 1.1994x over previous
#include <cuda_runtime.h>
#include <cstdint>
#include <cstddef>

#define NNODES 4096
#define INDIM 256
#define HID 64
#define LOG2E 1.4426950408889634f
#define SHIFT 4.0f

// ---------------- scratch (no allocation allowed) ----------------
__device__ float g_wh1[4 * NNODES * HID];     // [H][N][64] fp32 (for srcdst)
__device__ float g_x2[NNODES * 256];          // concat heads [N][256]
__device__ float g_wh2[NNODES * HID];
__device__ float g_srcP1[4 * NNODES];
__device__ float g_srcQ1[4 * NNODES];
__device__ float g_dstP1[4 * NNODES];
__device__ float g_dstQ1[4 * NNODES];
__device__ float g_srcP2[NNODES];
__device__ float g_srcQ2[NNODES];
__device__ float g_dstP2[NNODES];
__device__ float g_dstQ2[NNODES];
__device__ float g_pnum[2 * NNODES * 256];    // partial numerators
__device__ float g_pden[8 * NNODES];          // [z][H][N]
__device__ uint32_t g_mask[NNODES * 128];     // adjacency bitmask
__device__ uint4 g_whF1[4 * 128 * 256];       // f16 frag tensor L1: [H][chunk][2][8][32] uint2
__device__ uint4 g_whF2[128 * 256];           // f16 frag tensor L2

// ---------------- helpers ------------------------------------------------------
__device__ __forceinline__ uint32_t pack_f16x2(float lo, float hi) {
    uint32_t r; asm("cvt.rn.f16x2.f32 %0, %1, %2;" : "=r"(r) : "f"(hi), "f"(lo)); return r;
}
__device__ __forceinline__ uint32_t hadd2(uint32_t a, uint32_t b) {
    uint32_t r; asm("add.rn.f16x2 %0, %1, %2;" : "=r"(r) : "r"(a), "r"(b)); return r;
}
__device__ __forceinline__ uint32_t hmax2(uint32_t a, uint32_t b) {
    uint32_t r; asm("max.f16x2 %0, %1, %2;" : "=r"(r) : "r"(a), "r"(b)); return r;
}
__device__ __forceinline__ uint32_t hex2(uint32_t a) {
    uint32_t r; asm("ex2.approx.f16x2 %0, %1;" : "=r"(r) : "r"(a)); return r;
}
// halfword masks from 2 bits: lo16 = bit0 ? 0xFFFF : 0, hi16 = bit1 ? 0xFFFF : 0
__device__ __forceinline__ uint32_t bits2mask(uint32_t v) {
    return (v & 1u) * 0xFFFFu + (v & 2u) * 0x7FFF8000u;
}
__device__ __forceinline__ void mma_f16(float* c,
                                        uint32_t a0, uint32_t a1, uint32_t a2, uint32_t a3,
                                        uint32_t b0, uint32_t b1) {
    asm volatile(
        "mma.sync.aligned.m16n8k16.row.col.f32.f16.f16.f32 "
        "{%0,%1,%2,%3}, {%4,%5,%6,%7}, {%8,%9}, {%0,%1,%2,%3};"
        : "+f"(c[0]), "+f"(c[1]), "+f"(c[2]), "+f"(c[3])
        : "r"(a0), "r"(a1), "r"(a2), "r"(a3), "r"(b0), "r"(b1));
}
__device__ __forceinline__ void cp16(void* dst, const void* src) {
    uint32_t d = (uint32_t)__cvta_generic_to_shared(dst);
    asm volatile("cp.async.cg.shared.global [%0], [%1], 16;" :: "r"(d), "l"(src));
}
#define CP_COMMIT() asm volatile("cp.async.commit_group;" ::: "memory")
#define CP_WAIT(n)  asm volatile("cp.async.wait_group %0;" :: "n"(n) : "memory")
#define ONES_F16X2  0x3C003C00u

// ---------------- adjacency -> bitmask ----------------------------------------
__global__ void pack_adj_kernel(const int* __restrict__ adj, uint32_t* __restrict__ maskb)
{
    const int warp = threadIdx.x >> 5, lane = threadIdx.x & 31;
    const int r = blockIdx.x * 8 + warp;
    const int* row = adj + (size_t)r * NNODES;
    #pragma unroll
    for (int wg = 0; wg < 4; wg++) {
        uint32_t kept = 0;
        #pragma unroll
        for (int ww = 0; ww < 32; ww++) {
            int v = row[(wg * 32 + ww) * 32 + lane];
            uint32_t b = __ballot_sync(0xffffffffu, v > 0);
            if (lane == ww) kept = b;
        }
        maskb[(size_t)r * 128 + wg * 32 + lane] = kept;
    }
}

// ---------------- GEMM: Y = X@W + B (fp32) + f16 MMA-fragment tensor ----------
__global__ void __launch_bounds__(256) gemm_bias_kernel(
    const float* __restrict__ X, const float* __restrict__ W,
    const float* __restrict__ B, float* __restrict__ Y, uint4* __restrict__ YF)
{
    const int h  = blockIdx.y;
    const int i0 = blockIdx.x * 64;
    const int t  = threadIdx.x;
    const int dg = t & 15;
    const int ig = t >> 4;

    __shared__ float Xs[2][64][16];
    __shared__ float Ws[2][16][64];

    const float* Wh = W + (size_t)h * INDIM * HID;
    const int xrow = t >> 2, xseg = t & 3;
    const int wrow = t >> 4, wseg = t & 15;

    auto stage = [&](int buf, int kc) {
        cp16(&Xs[buf][xrow][xseg * 4], X + (size_t)(i0 + xrow) * INDIM + kc + xseg * 4);
        cp16(&Ws[buf][wrow][wseg * 4], Wh + (size_t)(kc + wrow) * HID + wseg * 4);
    };

    stage(0, 0);
    CP_COMMIT();

    float acc[4][4] = {};
    for (int kk = 0; kk < INDIM / 16; kk++) {
        if (kk + 1 < INDIM / 16) {
            stage((kk + 1) & 1, (kk + 1) * 16);
            CP_COMMIT();
            CP_WAIT(1);
        } else {
            CP_WAIT(0);
        }
        __syncthreads();
        const int buf = kk & 1;
        #pragma unroll
        for (int k = 0; k < 16; k++) {
            float4 wv = *(const float4*)(&Ws[buf][k][dg * 4]);
            float x0 = Xs[buf][ig * 4 + 0][k];
            float x1 = Xs[buf][ig * 4 + 1][k];
            float x2 = Xs[buf][ig * 4 + 2][k];
            float x3 = Xs[buf][ig * 4 + 3][k];
            acc[0][0] += x0 * wv.x; acc[0][1] += x0 * wv.y; acc[0][2] += x0 * wv.z; acc[0][3] += x0 * wv.w;
            acc[1][0] += x1 * wv.x; acc[1][1] += x1 * wv.y; acc[1][2] += x1 * wv.z; acc[1][3] += x1 * wv.w;
            acc[2][0] += x2 * wv.x; acc[2][1] += x2 * wv.y; acc[2][2] += x2 * wv.z; acc[2][3] += x2 * wv.w;
            acc[3][0] += x3 * wv.x; acc[3][1] += x3 * wv.y; acc[3][2] += x3 * wv.z; acc[3][3] += x3 * wv.w;
        }
        __syncthreads();
    }

    float4 bv = *(const float4*)(B + h * HID + dg * 4);
    float bb[4] = {bv.x, bv.y, bv.z, bv.w};
    #pragma unroll
    for (int ii = 0; ii < 4; ii++) {
        float4 r;
        r.x = acc[ii][0] + bb[0];
        r.y = acc[ii][1] + bb[1];
        r.z = acc[ii][2] + bb[2];
        r.w = acc[ii][3] + bb[3];
        *(float4*)(Y + ((size_t)h * NNODES + i0 + ig * 4 + ii) * HID + dg * 4) = r;
    }
    // f16 fragment tensor: [h][chunk][ks][nt][lane] uint2, halves by (j%16)/8
    uint32_t* fb = (uint32_t*)(YF + (size_t)h * 128 * 256);
    #pragma unroll
    for (int c = 0; c < 4; c++) {
        const int d = dg * 4 + c;
        const int nt = d >> 3;
        const int lnb = (d & 7) * 4;
        #pragma unroll
        for (int p = 0; p < 2; p++) {
            const int jp = i0 + ig * 4 + 2 * p;
            const int chunk = jp >> 5;
            const int ks = (jp >> 4) & 1;
            const int rr = jp & 15;
            const int lanei = lnb + ((rr & 7) >> 1);
            uint32_t val = pack_f16x2(acc[2 * p][c] + bb[c], acc[2 * p + 1][c] + bb[c]);
            size_t idx = (((size_t)chunk * 2 + ks) * 8 + nt) * 32 + lanei;
            fb[idx * 2 + (rr >> 3)] = val;
        }
    }
}

// ---------------- src/dst projections (leaky pre-factored, log2e, shifted) ----
__global__ void srcdst_kernel(const float* __restrict__ wh,
                              const float* __restrict__ asrc,
                              const float* __restrict__ adst,
                              const float* __restrict__ ab,
                              float* __restrict__ osrcP, float* __restrict__ osrcQ,
                              float* __restrict__ odstP, float* __restrict__ odstQ,
                              int total)
{
    int gw = (blockIdx.x * blockDim.x + threadIdx.x) >> 5;
    int lane = threadIdx.x & 31;
    if (gw >= total) return;
    int h = gw >> 12;
    const float* row = wh + (size_t)gw * HID;
    float v0 = row[lane], v1 = row[lane + 32];
    float s = v0 * asrc[h * HID + lane] + v1 * asrc[h * HID + lane + 32];
    float d = v0 * adst[h * HID + lane] + v1 * adst[h * HID + lane + 32];
    #pragma unroll
    for (int o = 16; o > 0; o >>= 1) {
        s += __shfl_xor_sync(0xffffffffu, s, o);
        d += __shfl_xor_sync(0xffffffffu, d, o);
    }
    if (lane == 0) {
        float u = (s + ab[h]) * LOG2E;
        float v = d * LOG2E;
        osrcP[gw] = u - SHIFT;
        osrcQ[gw] = 0.2f * u - SHIFT;
        odstP[gw] = v;
        odstQ[gw] = 0.2f * v;
    }
}

// ---------------- fused attention: f16x2 scores + mma m16n8k16 f16 -------------
__global__ void __launch_bounds__(256, 2) attn_mma_kernel(
    const uint4* __restrict__ whF,      // [H][128][2][8][32] uint2 (as uint4*)
    const float* __restrict__ srcP, const float* __restrict__ srcQ,  // [H][N]
    const float* __restrict__ dstP, const float* __restrict__ dstQ,  // [H][N]
    const uint32_t* __restrict__ maskb, // [N][128]
    float* __restrict__ pnum,           // [z][N][pcols]
    float* __restrict__ pden,           // [z][H][N]
    int pcols, int nheads)
{
    __shared__ alignas(16) uint2 bfrag[3][2][8][32];   // 3-stage, 4KB each
    __shared__ uint2 dsts2[1024];                      // (dstP2, dstQ2) per j-pair

    const int h    = blockIdx.y;
    const int t    = threadIdx.x;
    const int lane = t & 31;
    const int warp = t >> 5;
    const int gid  = lane >> 2;
    const int tig  = lane & 3;
    const int i0   = blockIdx.x * 128;
    const int z       = blockIdx.z;
    const int jsplit  = gridDim.z;
    const int nchunks = (NNODES / 32) / jsplit;
    const int jc0     = z * nchunks * 32;

    const int hN = h * NNODES;
    // stage dst pairs once (packed f16x2)
    for (int q = t; q < nchunks * 16; q += 256) {
        int j = jc0 + 2 * q;
        uint2 v;
        v.x = pack_f16x2(dstP[hN + j], dstP[hN + j + 1]);
        v.y = pack_f16x2(dstQ[hN + j], dstQ[hN + j + 1]);
        dsts2[q] = v;
    }

    const int iA = i0 + warp * 16 + gid;
    const int iB = iA + 8;
    const uint32_t srcP2A = pack_f16x2(srcP[hN + iA], srcP[hN + iA]);
    const uint32_t srcQ2A = pack_f16x2(srcQ[hN + iA], srcQ[hN + iA]);
    const uint32_t srcP2B = pack_f16x2(srcP[hN + iB], srcP[hN + iB]);
    const uint32_t srcQ2B = pack_f16x2(srcQ[hN + iB], srcQ[hN + iB]);
    const uint32_t* mApt = maskb + (size_t)iA * 128 + (jc0 >> 5);
    const uint32_t* mBpt = maskb + (size_t)iB * 128 + (jc0 >> 5);

    const uint2* gsrc = (const uint2*)whF + ((size_t)h * 128 + (jc0 >> 5)) * 512;
    uint2* sbase = &bfrag[0][0][0][0];

    float acc[9][4];
    #pragma unroll
    for (int n = 0; n < 9; n++)
        #pragma unroll
        for (int r = 0; r < 4; r++) acc[n][r] = 0.f;

    // prologue: stage chunks 0,1
    cp16(sbase + 0 * 512 + t * 2, gsrc + 0 * 512 + t * 2);
    CP_COMMIT();
    cp16(sbase + 1 * 512 + t * 2, gsrc + 1 * 512 + t * 2);
    CP_COMMIT();

    uint4 wA4, wB4;
    int buf = 0, nbuf = 2;
    for (int chunk = 0; chunk < nchunks; chunk++) {
        if ((chunk & 3) == 0) {
            wA4 = *(const uint4*)mApt; mApt += 4;
            wB4 = *(const uint4*)mBpt; mBpt += 4;
        }
        const int cc = chunk & 3;
        const uint32_t wAw = (cc == 0) ? wA4.x : (cc == 1) ? wA4.y : (cc == 2) ? wA4.z : wA4.w;
        const uint32_t wBw = (cc == 0) ? wB4.x : (cc == 1) ? wB4.y : (cc == 2) ? wB4.z : wB4.w;

        CP_WAIT(1);
        __syncthreads();
        if (chunk + 2 < nchunks)
            cp16(sbase + nbuf * 512 + t * 2, gsrc + (size_t)(chunk + 2) * 512 + t * 2);
        CP_COMMIT();

        // A fragments: masked exp2 scores in f16x2
        uint32_t aA[2][2], aB[2][2];
        #pragma unroll
        for (int ks = 0; ks < 2; ks++) {
            const int pidx = chunk * 16 + ks * 8 + tig;
            uint2 dd0 = dsts2[pidx];       // j pair (2tig, 2tig+1)
            uint2 dd1 = dsts2[pidx + 4];   // j pair (2tig+8, 2tig+9)

            // mask bits -> halfword masks (branch-free arithmetic, provable)
            uint32_t vA = wAw >> (16 * ks + 2 * tig);
            uint32_t vB = wBw >> (16 * ks + 2 * tig);
            uint32_t mskA0 = bits2mask(vA);
            uint32_t mskA1 = bits2mask(vA >> 8);
            uint32_t mskB0 = bits2mask(vB);
            uint32_t mskB1 = bits2mask(vB >> 8);

            uint32_t eA0 = hex2(hmax2(hadd2(srcP2A, dd0.x), hadd2(srcQ2A, dd0.y))) & mskA0;
            uint32_t eA1 = hex2(hmax2(hadd2(srcP2A, dd1.x), hadd2(srcQ2A, dd1.y))) & mskA1;
            uint32_t eB0 = hex2(hmax2(hadd2(srcP2B, dd0.x), hadd2(srcQ2B, dd0.y))) & mskB0;
            uint32_t eB1 = hex2(hmax2(hadd2(srcP2B, dd1.x), hadd2(srcQ2B, dd1.y))) & mskB1;

            aA[ks][0] = eA0; aA[ks][1] = eA1;
            aB[ks][0] = eB0; aB[ks][1] = eB1;
        }

        // MMAs: 8 output tiles + 1 ones tile (den) per ks
        #pragma unroll
        for (int ks = 0; ks < 2; ks++) {
            const uint2* bk = &bfrag[buf][ks][0][lane];
            #pragma unroll
            for (int nt = 0; nt < 8; nt++) {
                uint2 b = bk[nt * 32];
                mma_f16(acc[nt], aA[ks][0], aB[ks][0], aA[ks][1], aB[ks][1], b.x, b.y);
            }
            mma_f16(acc[8], aA[ks][0], aB[ks][0], aA[ks][1], aB[ks][1], ONES_F16X2, ONES_F16X2);
        }

        buf  = (buf == 2)  ? 0 : buf + 1;
        nbuf = (nbuf == 2) ? 0 : nbuf + 1;
    }

    const float denA = acc[8][0];   // ones-column: row gid
    const float denB = acc[8][2];   // ones-column: row gid+8

    float* pA = pnum + ((size_t)z * NNODES + iA) * pcols + h * 64 + 2 * tig;
    float* pB = pnum + ((size_t)z * NNODES + iB) * pcols + h * 64 + 2 * tig;
    #pragma unroll
    for (int nt = 0; nt < 8; nt++) {
        float2 va, vb;
        va.x = acc[nt][0]; va.y = acc[nt][1];
        vb.x = acc[nt][2]; vb.y = acc[nt][3];
        *(float2*)(pA + nt * 8) = va;
        *(float2*)(pB + nt * 8) = vb;
    }
    if (tig == 0) {
        pden[((size_t)z * nheads + h) * NNODES + iA] = denA;
        pden[((size_t)z * nheads + h) * NNODES + iB] = denB;
    }
}

// ---------------- partial reduce + softmax divide + elu -----------------------
__global__ void reduce_kernel(const float* __restrict__ pnum,
                              const float* __restrict__ pden,
                              float* __restrict__ out,
                              int zn, int cols, int cqs, int H)
{
    int idx = blockIdx.x * blockDim.x + threadIdx.x;
    int i = idx >> cqs;
    int c = (idx & ((1 << cqs) - 1)) << 2;
    int h = c >> 6;
    float den = 0.f;
    for (int zz = 0; zz < zn; zz++)
        den += pden[((size_t)zz * H + h) * NNODES + i];
    float4 a = *(const float4*)(pnum + ((size_t)i) * cols + c);
    for (int zz = 1; zz < zn; zz++) {
        float4 b = *(const float4*)(pnum + ((size_t)zz * NNODES + i) * cols + c);
        a.x += b.x; a.y += b.y; a.z += b.z; a.w += b.w;
    }
    float inv = 1.f / den;
    float v[4] = {a.x * inv, a.y * inv, a.z * inv, a.w * inv};
    #pragma unroll
    for (int r = 0; r < 4; r++) v[r] = (v[r] > 0.f) ? v[r] : expm1f(v[r]);
    float4 o4; o4.x = v[0]; o4.y = v[1]; o4.z = v[2]; o4.w = v[3];
    *(float4*)(out + (size_t)i * cols + c) = o4;
}

// ---------------- launch ------------------------------------------------------
extern "C" void kernel_launch(void* const* d_in, const int* in_sizes, int n_in,
                              void* d_out, int out_size)
{
    const float* h      = (const float*)d_in[0];
    const int*   adj    = (const int*)  d_in[1];
    const float* Wh     = (const float*)d_in[2];
    const float* bWh    = (const float*)d_in[3];
    const float* a_src  = (const float*)d_in[4];
    const float* a_dst  = (const float*)d_in[5];
    const float* a_b    = (const float*)d_in[6];
    const float* Wo     = (const float*)d_in[7];
    const float* bWo    = (const float*)d_in[8];
    const float* ao_src = (const float*)d_in[9];
    const float* ao_dst = (const float*)d_in[10];
    const float* ao_b   = (const float*)d_in[11];
    float* out = (float*)d_out;

    float *wh1, *x2, *wh2, *pnum, *pden;
    float *sP1, *sQ1, *dP1, *dQ1, *sP2, *sQ2, *dP2, *dQ2;
    uint32_t* maskb;
    uint4 *whF1, *whF2;
    cudaGetSymbolAddress((void**)&wh1,  g_wh1);
    cudaGetSymbolAddress((void**)&x2,   g_x2);
    cudaGetSymbolAddress((void**)&wh2,  g_wh2);
    cudaGetSymbolAddress((void**)&sP1, g_srcP1);
    cudaGetSymbolAddress((void**)&sQ1, g_srcQ1);
    cudaGetSymbolAddress((void**)&dP1, g_dstP1);
    cudaGetSymbolAddress((void**)&dQ1, g_dstQ1);
    cudaGetSymbolAddress((void**)&sP2, g_srcP2);
    cudaGetSymbolAddress((void**)&sQ2, g_srcQ2);
    cudaGetSymbolAddress((void**)&dP2, g_dstP2);
    cudaGetSymbolAddress((void**)&dQ2, g_dstQ2);
    cudaGetSymbolAddress((void**)&pnum, g_pnum);
    cudaGetSymbolAddress((void**)&pden, g_pden);
    cudaGetSymbolAddress((void**)&maskb, g_mask);
    cudaGetSymbolAddress((void**)&whF1, g_whF1);
    cudaGetSymbolAddress((void**)&whF2, g_whF2);

    pack_adj_kernel<<<NNODES / 8, 256>>>(adj, maskb);

    // Layer 1 (jsplit=2)
    gemm_bias_kernel<<<dim3(NNODES / 64, 4), 256>>>(h, Wh, bWh, wh1, whF1);
    srcdst_kernel<<<4 * 512, 256>>>(wh1, a_src, a_dst, a_b, sP1, sQ1, dP1, dQ1, 4 * NNODES);
    attn_mma_kernel<<<dim3(NNODES / 128, 4, 2), 256>>>(whF1, sP1, sQ1, dP1, dQ1, maskb, pnum, pden, 256, 4);
    reduce_kernel<<<(NNODES * 64) / 256, 256>>>(pnum, pden, x2, 2, 256, 6, 4);

    // Layer 2 (jsplit=8)
    gemm_bias_kernel<<<dim3(NNODES / 64, 1), 256>>>(x2, Wo, bWo, wh2, whF2);
    srcdst_kernel<<<512, 256>>>(wh2, ao_src, ao_dst, ao_b, sP2, sQ2, dP2, dQ2, NNODES);
    attn_mma_kernel<<<dim3(NNODES / 128, 1, 8), 256>>>(whF2, sP2, sQ2, dP2, dQ2, maskb, pnum, pden, 64, 1);
    reduce_kernel<<<(NNODES * 16) / 256, 256>>>(pnum, pden, out, 8, 64, 4, 1);
}

// round 8
// speedup vs baseline: 7.9375x; 1.0457x over previous
#include <cuda_runtime.h>
#include <cstdint>
#include <cstddef>

#define NNODES 4096
#define INDIM 256
#define HID 64
#define LOG2E 1.4426950408889634f
#define SHIFT 4.0f

// ---------------- scratch (no allocation allowed) ----------------
__device__ float g_wh1[4 * NNODES * HID];     // [H][N][64] fp32 (for srcdst)
__device__ float g_x2[NNODES * 256];          // concat heads [N][256]
__device__ float g_wh2[NNODES * HID];
__device__ float g_srcP1[4 * NNODES];
__device__ float g_srcQ1[4 * NNODES];
__device__ float g_dstP1[4 * NNODES];
__device__ float g_dstQ1[4 * NNODES];
__device__ float g_srcP2[NNODES];
__device__ float g_srcQ2[NNODES];
__device__ float g_dstP2[NNODES];
__device__ float g_dstQ2[NNODES];
__device__ float g_pnum[2 * NNODES * 256];    // partial numerators
__device__ float g_pden[8 * NNODES];          // [z][H][N]
__device__ uint32_t g_mask[NNODES * 128];     // adjacency bitmask
__device__ uint4 g_whF1[4 * 64 * 512];        // f16 frag tensor L1: [H][c64][4ks][4ntp][32lane] uint4
__device__ uint4 g_whF2[64 * 512];            // f16 frag tensor L2

// ---------------- helpers ------------------------------------------------------
__device__ __forceinline__ uint32_t pack_f16x2(float lo, float hi) {
    uint32_t r; asm("cvt.rn.f16x2.f32 %0, %1, %2;" : "=r"(r) : "f"(hi), "f"(lo)); return r;
}
__device__ __forceinline__ uint32_t hadd2(uint32_t a, uint32_t b) {
    uint32_t r; asm("add.rn.f16x2 %0, %1, %2;" : "=r"(r) : "r"(a), "r"(b)); return r;
}
__device__ __forceinline__ uint32_t hmax2(uint32_t a, uint32_t b) {
    uint32_t r; asm("max.f16x2 %0, %1, %2;" : "=r"(r) : "r"(a), "r"(b)); return r;
}
__device__ __forceinline__ uint32_t hex2(uint32_t a) {
    uint32_t r; asm("ex2.approx.f16x2 %0, %1;" : "=r"(r) : "r"(a)); return r;
}
// halfword masks from 2 bits: lo16 = bit0 ? 0xFFFF : 0, hi16 = bit1 ? 0xFFFF : 0
__device__ __forceinline__ uint32_t bits2mask(uint32_t v) {
    return (v & 1u) * 0xFFFFu + (v & 2u) * 0x7FFF8000u;
}
__device__ __forceinline__ void mma_f16(float* c,
                                        uint32_t a0, uint32_t a1, uint32_t a2, uint32_t a3,
                                        uint32_t b0, uint32_t b1) {
    asm volatile(
        "mma.sync.aligned.m16n8k16.row.col.f32.f16.f16.f32 "
        "{%0,%1,%2,%3}, {%4,%5,%6,%7}, {%8,%9}, {%0,%1,%2,%3};"
        : "+f"(c[0]), "+f"(c[1]), "+f"(c[2]), "+f"(c[3])
        : "r"(a0), "r"(a1), "r"(a2), "r"(a3), "r"(b0), "r"(b1));
}
__device__ __forceinline__ void cp16(void* dst, const void* src) {
    uint32_t d = (uint32_t)__cvta_generic_to_shared(dst);
    asm volatile("cp.async.cg.shared.global [%0], [%1], 16;" :: "r"(d), "l"(src));
}
#define CP_COMMIT() asm volatile("cp.async.commit_group;" ::: "memory")
#define CP_WAIT(n)  asm volatile("cp.async.wait_group %0;" :: "n"(n) : "memory")
#define ONES_F16X2  0x3C003C00u

// ---------------- adjacency -> bitmask ----------------------------------------
__global__ void pack_adj_kernel(const int* __restrict__ adj, uint32_t* __restrict__ maskb)
{
    const int warp = threadIdx.x >> 5, lane = threadIdx.x & 31;
    const int r = blockIdx.x * 8 + warp;
    const int* row = adj + (size_t)r * NNODES;
    #pragma unroll
    for (int wg = 0; wg < 4; wg++) {
        uint32_t kept = 0;
        #pragma unroll
        for (int ww = 0; ww < 32; ww++) {
            int v = row[(wg * 32 + ww) * 32 + lane];
            uint32_t b = __ballot_sync(0xffffffffu, v > 0);
            if (lane == ww) kept = b;
        }
        maskb[(size_t)r * 128 + wg * 32 + lane] = kept;
    }
}

// ---------------- GEMM: Y = X@W + B (fp32) + paired f16 fragment tensor -------
__global__ void __launch_bounds__(256) gemm_bias_kernel(
    const float* __restrict__ X, const float* __restrict__ W,
    const float* __restrict__ B, float* __restrict__ Y, uint4* __restrict__ YF)
{
    const int h  = blockIdx.y;
    const int i0 = blockIdx.x * 64;
    const int t  = threadIdx.x;
    const int dg = t & 15;
    const int ig = t >> 4;

    __shared__ float Xs[2][64][16];
    __shared__ float Ws[2][16][64];

    const float* Wh = W + (size_t)h * INDIM * HID;
    const int xrow = t >> 2, xseg = t & 3;
    const int wrow = t >> 4, wseg = t & 15;

    auto stage = [&](int buf, int kc) {
        cp16(&Xs[buf][xrow][xseg * 4], X + (size_t)(i0 + xrow) * INDIM + kc + xseg * 4);
        cp16(&Ws[buf][wrow][wseg * 4], Wh + (size_t)(kc + wrow) * HID + wseg * 4);
    };

    stage(0, 0);
    CP_COMMIT();

    float acc[4][4] = {};
    for (int kk = 0; kk < INDIM / 16; kk++) {
        if (kk + 1 < INDIM / 16) {
            stage((kk + 1) & 1, (kk + 1) * 16);
            CP_COMMIT();
            CP_WAIT(1);
        } else {
            CP_WAIT(0);
        }
        __syncthreads();
        const int buf = kk & 1;
        #pragma unroll
        for (int k = 0; k < 16; k++) {
            float4 wv = *(const float4*)(&Ws[buf][k][dg * 4]);
            float x0 = Xs[buf][ig * 4 + 0][k];
            float x1 = Xs[buf][ig * 4 + 1][k];
            float x2 = Xs[buf][ig * 4 + 2][k];
            float x3 = Xs[buf][ig * 4 + 3][k];
            acc[0][0] += x0 * wv.x; acc[0][1] += x0 * wv.y; acc[0][2] += x0 * wv.z; acc[0][3] += x0 * wv.w;
            acc[1][0] += x1 * wv.x; acc[1][1] += x1 * wv.y; acc[1][2] += x1 * wv.z; acc[1][3] += x1 * wv.w;
            acc[2][0] += x2 * wv.x; acc[2][1] += x2 * wv.y; acc[2][2] += x2 * wv.z; acc[2][3] += x2 * wv.w;
            acc[3][0] += x3 * wv.x; acc[3][1] += x3 * wv.y; acc[3][2] += x3 * wv.z; acc[3][3] += x3 * wv.w;
        }
        __syncthreads();
    }

    float4 bv = *(const float4*)(B + h * HID + dg * 4);
    float bb[4] = {bv.x, bv.y, bv.z, bv.w};
    #pragma unroll
    for (int ii = 0; ii < 4; ii++) {
        float4 r;
        r.x = acc[ii][0] + bb[0];
        r.y = acc[ii][1] + bb[1];
        r.z = acc[ii][2] + bb[2];
        r.w = acc[ii][3] + bb[3];
        *(float4*)(Y + ((size_t)h * NNODES + i0 + ig * 4 + ii) * HID + dg * 4) = r;
    }
    // paired f16 fragment tensor: [h][c64][ks][ntp][lane] uint4
    //   uint4 words: {b0(nt=2ntp), b1(nt=2ntp), b0(nt=2ntp+1), b1(nt=2ntp+1)}
    uint32_t* fb = (uint32_t*)(YF + (size_t)h * 64 * 512);
    #pragma unroll
    for (int c = 0; c < 4; c++) {
        const int d = dg * 4 + c;
        const int ntp = d >> 4;
        const int sub = (d >> 3) & 1;
        const int lnb = (d & 7) * 4;
        #pragma unroll
        for (int p = 0; p < 2; p++) {
            const int jp = i0 + ig * 4 + 2 * p;
            const int c64 = jp >> 6;
            const int ks = (jp >> 4) & 3;
            const int rr = jp & 15;
            const int lanei = lnb + ((rr & 7) >> 1);
            const int word = sub * 2 + (rr >> 3);
            uint32_t val = pack_f16x2(acc[2 * p][c] + bb[c], acc[2 * p + 1][c] + bb[c]);
            size_t idx = (((size_t)c64 * 4 + ks) * 4 + ntp) * 32 + lanei;
            fb[idx * 4 + word] = val;
        }
    }
}

// ---------------- src/dst projections (leaky pre-factored, log2e, shifted) ----
__global__ void srcdst_kernel(const float* __restrict__ wh,
                              const float* __restrict__ asrc,
                              const float* __restrict__ adst,
                              const float* __restrict__ ab,
                              float* __restrict__ osrcP, float* __restrict__ osrcQ,
                              float* __restrict__ odstP, float* __restrict__ odstQ,
                              int total)
{
    int gw = (blockIdx.x * blockDim.x + threadIdx.x) >> 5;
    int lane = threadIdx.x & 31;
    if (gw >= total) return;
    int h = gw >> 12;
    const float* row = wh + (size_t)gw * HID;
    float v0 = row[lane], v1 = row[lane + 32];
    float s = v0 * asrc[h * HID + lane] + v1 * asrc[h * HID + lane + 32];
    float d = v0 * adst[h * HID + lane] + v1 * adst[h * HID + lane + 32];
    #pragma unroll
    for (int o = 16; o > 0; o >>= 1) {
        s += __shfl_xor_sync(0xffffffffu, s, o);
        d += __shfl_xor_sync(0xffffffffu, d, o);
    }
    if (lane == 0) {
        float u = (s + ab[h]) * LOG2E;
        float v = d * LOG2E;
        osrcP[gw] = u - SHIFT;
        osrcQ[gw] = 0.2f * u - SHIFT;
        odstP[gw] = v;
        odstQ[gw] = 0.2f * v;
    }
}

// ---------------- fused attention: 64-j chunks, f16x2 scores, mma f16 ---------
__global__ void __launch_bounds__(256, 2) attn_mma_kernel(
    const uint4* __restrict__ whF,      // [H][64][4][4][32] uint4
    const float* __restrict__ srcP, const float* __restrict__ srcQ,  // [H][N]
    const float* __restrict__ dstP, const float* __restrict__ dstQ,  // [H][N]
    const uint32_t* __restrict__ maskb, // [N][128]
    float* __restrict__ pnum,           // [z][N][pcols]
    float* __restrict__ pden,           // [z][H][N]
    int pcols, int nheads)
{
    __shared__ alignas(16) uint4 bfragq[3][4][4][32];  // 3-stage, 8KB each
    __shared__ uint2 dsts2[1024];                      // (dstP2, dstQ2) per j-pair

    const int h    = blockIdx.y;
    const int t    = threadIdx.x;
    const int lane = t & 31;
    const int warp = t >> 5;
    const int gid  = lane >> 2;
    const int tig  = lane & 3;
    const int i0   = blockIdx.x * 128;
    const int z       = blockIdx.z;
    const int jsplit  = gridDim.z;
    const int nchunks = (NNODES / 64) / jsplit;
    const int jc0     = z * nchunks * 64;

    const int hN = h * NNODES;
    // stage dst pairs once (packed f16x2)
    for (int q = t; q < nchunks * 32; q += 256) {
        int j = jc0 + 2 * q;
        uint2 v;
        v.x = pack_f16x2(dstP[hN + j], dstP[hN + j + 1]);
        v.y = pack_f16x2(dstQ[hN + j], dstQ[hN + j + 1]);
        dsts2[q] = v;
    }

    const int iA = i0 + warp * 16 + gid;
    const int iB = iA + 8;
    const uint32_t srcP2A = pack_f16x2(srcP[hN + iA], srcP[hN + iA]);
    const uint32_t srcQ2A = pack_f16x2(srcQ[hN + iA], srcQ[hN + iA]);
    const uint32_t srcP2B = pack_f16x2(srcP[hN + iB], srcP[hN + iB]);
    const uint32_t srcQ2B = pack_f16x2(srcQ[hN + iB], srcQ[hN + iB]);
    const uint2* mA2 = (const uint2*)(maskb + (size_t)iA * 128 + (jc0 >> 5));
    const uint2* mB2 = (const uint2*)(maskb + (size_t)iB * 128 + (jc0 >> 5));

    const uint4* gsrc = whF + ((size_t)h * 64 + (jc0 >> 6)) * 512;

    float acc[9][4];
    #pragma unroll
    for (int n = 0; n < 9; n++)
        #pragma unroll
        for (int r = 0; r < 4; r++) acc[n][r] = 0.f;

    // prologue: stage chunks 0,1 (512 uint4 each = 2 cp16/thread)
    {
        uint4* d0 = &bfragq[0][0][0][0];
        cp16(d0 + t, gsrc + t);
        cp16(d0 + t + 256, gsrc + t + 256);
        CP_COMMIT();
        uint4* d1 = &bfragq[1][0][0][0];
        cp16(d1 + t, gsrc + 512 + t);
        cp16(d1 + t + 256, gsrc + 512 + t + 256);
        CP_COMMIT();
    }

    int buf = 0, nbuf = 2;
    for (int chunk = 0; chunk < nchunks; chunk++) {
        const uint2 wAu = mA2[chunk];
        const uint2 wBu = mB2[chunk];

        CP_WAIT(1);
        __syncthreads();
        if (chunk + 2 < nchunks) {
            uint4* dn = &bfragq[nbuf][0][0][0];
            const uint4* sn = gsrc + (size_t)(chunk + 2) * 512;
            cp16(dn + t, sn + t);
            cp16(dn + t + 256, sn + t + 256);
        }
        CP_COMMIT();

        #pragma unroll
        for (int ks = 0; ks < 4; ks++) {
            uint32_t vA = ((ks < 2) ? wAu.x : wAu.y) >> ((ks & 1) * 16 + 2 * tig);
            uint32_t vB = ((ks < 2) ? wBu.x : wBu.y) >> ((ks & 1) * 16 + 2 * tig);
            uint32_t mskA0 = bits2mask(vA);
            uint32_t mskA1 = bits2mask(vA >> 8);
            uint32_t mskB0 = bits2mask(vB);
            uint32_t mskB1 = bits2mask(vB >> 8);

            const int pidx = chunk * 32 + ks * 8 + tig;
            uint2 dd0 = dsts2[pidx];       // j pair (2tig, 2tig+1)
            uint2 dd1 = dsts2[pidx + 4];   // j pair (2tig+8, 2tig+9)

            uint32_t eA0 = hex2(hmax2(hadd2(srcP2A, dd0.x), hadd2(srcQ2A, dd0.y))) & mskA0;
            uint32_t eA1 = hex2(hmax2(hadd2(srcP2A, dd1.x), hadd2(srcQ2A, dd1.y))) & mskA1;
            uint32_t eB0 = hex2(hmax2(hadd2(srcP2B, dd0.x), hadd2(srcQ2B, dd0.y))) & mskB0;
            uint32_t eB1 = hex2(hmax2(hadd2(srcP2B, dd1.x), hadd2(srcQ2B, dd1.y))) & mskB1;

            const uint4* bk = &bfragq[buf][ks][0][lane];
            #pragma unroll
            for (int ntp = 0; ntp < 4; ntp++) {
                uint4 b = bk[ntp * 32];
                mma_f16(acc[2 * ntp],     eA0, eB0, eA1, eB1, b.x, b.y);
                mma_f16(acc[2 * ntp + 1], eA0, eB0, eA1, eB1, b.z, b.w);
            }
            mma_f16(acc[8], eA0, eB0, eA1, eB1, ONES_F16X2, ONES_F16X2);
        }

        buf  = (buf == 2)  ? 0 : buf + 1;
        nbuf = (nbuf == 2) ? 0 : nbuf + 1;
    }

    const float denA = acc[8][0];   // ones-column: row gid
    const float denB = acc[8][2];   // ones-column: row gid+8

    float* pA = pnum + ((size_t)z * NNODES + iA) * pcols + h * 64 + 2 * tig;
    float* pB = pnum + ((size_t)z * NNODES + iB) * pcols + h * 64 + 2 * tig;
    #pragma unroll
    for (int nt = 0; nt < 8; nt++) {
        float2 va, vb;
        va.x = acc[nt][0]; va.y = acc[nt][1];
        vb.x = acc[nt][2]; vb.y = acc[nt][3];
        *(float2*)(pA + nt * 8) = va;
        *(float2*)(pB + nt * 8) = vb;
    }
    if (tig == 0) {
        pden[((size_t)z * nheads + h) * NNODES + iA] = denA;
        pden[((size_t)z * nheads + h) * NNODES + iB] = denB;
    }
}

// ---------------- partial reduce + softmax divide + elu -----------------------
__global__ void reduce_kernel(const float* __restrict__ pnum,
                              const float* __restrict__ pden,
                              float* __restrict__ out,
                              int zn, int cols, int cqs, int H)
{
    int idx = blockIdx.x * blockDim.x + threadIdx.x;
    int i = idx >> cqs;
    int c = (idx & ((1 << cqs) - 1)) << 2;
    int h = c >> 6;
    float den = 0.f;
    for (int zz = 0; zz < zn; zz++)
        den += pden[((size_t)zz * H + h) * NNODES + i];
    float4 a = *(const float4*)(pnum + ((size_t)i) * cols + c);
    for (int zz = 1; zz < zn; zz++) {
        float4 b = *(const float4*)(pnum + ((size_t)zz * NNODES + i) * cols + c);
        a.x += b.x; a.y += b.y; a.z += b.z; a.w += b.w;
    }
    float inv = 1.f / den;
    float v[4] = {a.x * inv, a.y * inv, a.z * inv, a.w * inv};
    #pragma unroll
    for (int r = 0; r < 4; r++) v[r] = (v[r] > 0.f) ? v[r] : expm1f(v[r]);
    float4 o4; o4.x = v[0]; o4.y = v[1]; o4.z = v[2]; o4.w = v[3];
    *(float4*)(out + (size_t)i * cols + c) = o4;
}

// ---------------- launch ------------------------------------------------------
extern "C" void kernel_launch(void* const* d_in, const int* in_sizes, int n_in,
                              void* d_out, int out_size)
{
    const float* h      = (const float*)d_in[0];
    const int*   adj    = (const int*)  d_in[1];
    const float* Wh     = (const float*)d_in[2];
    const float* bWh    = (const float*)d_in[3];
    const float* a_src  = (const float*)d_in[4];
    const float* a_dst  = (const float*)d_in[5];
    const float* a_b    = (const float*)d_in[6];
    const float* Wo     = (const float*)d_in[7];
    const float* bWo    = (const float*)d_in[8];
    const float* ao_src = (const float*)d_in[9];
    const float* ao_dst = (const float*)d_in[10];
    const float* ao_b   = (const float*)d_in[11];
    float* out = (float*)d_out;

    float *wh1, *x2, *wh2, *pnum, *pden;
    float *sP1, *sQ1, *dP1, *dQ1, *sP2, *sQ2, *dP2, *dQ2;
    uint32_t* maskb;
    uint4 *whF1, *whF2;
    cudaGetSymbolAddress((void**)&wh1,  g_wh1);
    cudaGetSymbolAddress((void**)&x2,   g_x2);
    cudaGetSymbolAddress((void**)&wh2,  g_wh2);
    cudaGetSymbolAddress((void**)&sP1, g_srcP1);
    cudaGetSymbolAddress((void**)&sQ1, g_srcQ1);
    cudaGetSymbolAddress((void**)&dP1, g_dstP1);
    cudaGetSymbolAddress((void**)&dQ1, g_dstQ1);
    cudaGetSymbolAddress((void**)&sP2, g_srcP2);
    cudaGetSymbolAddress((void**)&sQ2, g_srcQ2);
    cudaGetSymbolAddress((void**)&dP2, g_dstP2);
    cudaGetSymbolAddress((void**)&dQ2, g_dstQ2);
    cudaGetSymbolAddress((void**)&pnum, g_pnum);
    cudaGetSymbolAddress((void**)&pden, g_pden);
    cudaGetSymbolAddress((void**)&maskb, g_mask);
    cudaGetSymbolAddress((void**)&whF1, g_whF1);
    cudaGetSymbolAddress((void**)&whF2, g_whF2);

    pack_adj_kernel<<<NNODES / 8, 256>>>(adj, maskb);

    // Layer 1 (jsplit=2)
    gemm_bias_kernel<<<dim3(NNODES / 64, 4), 256>>>(h, Wh, bWh, wh1, whF1);
    srcdst_kernel<<<4 * 512, 256>>>(wh1, a_src, a_dst, a_b, sP1, sQ1, dP1, dQ1, 4 * NNODES);
    attn_mma_kernel<<<dim3(NNODES / 128, 4, 2), 256>>>(whF1, sP1, sQ1, dP1, dQ1, maskb, pnum, pden, 256, 4);
    reduce_kernel<<<(NNODES * 64) / 256, 256>>>(pnum, pden, x2, 2, 256, 6, 4);

    // Layer 2 (jsplit=8)
    gemm_bias_kernel<<<dim3(NNODES / 64, 1), 256>>>(x2, Wo, bWo, wh2, whF2);
    srcdst_kernel<<<512, 256>>>(wh2, ao_src, ao_dst, ao_b, sP2, sQ2, dP2, dQ2, NNODES);
    attn_mma_kernel<<<dim3(NNODES / 128, 1, 8), 256>>>(whF2, sP2, sQ2, dP2, dQ2, maskb, pnum, pden, 64, 1);
    reduce_kernel<<<(NNODES * 16) / 256, 256>>>(pnum, pden, out, 8, 64, 4, 1);
}

// round 9
// speedup vs baseline: 8.0561x; 1.0149x over previous
#include <cuda_runtime.h>
#include <cstdint>
#include <cstddef>

#define NNODES 4096
#define INDIM 256
#define HID 64
#define LOG2E 1.4426950408889634f
#define SHIFT 4.0f

// ---------------- scratch (no allocation allowed) ----------------
__device__ float g_wh1[4 * NNODES * HID];     // [H][N][64] fp32 (for srcdst)
__device__ float g_x2[NNODES * 256];          // concat heads [N][256]
__device__ float g_wh2[NNODES * HID];
__device__ float g_srcP1[4 * NNODES];
__device__ float g_srcQ1[4 * NNODES];
__device__ float g_dstP1[4 * NNODES];
__device__ float g_dstQ1[4 * NNODES];
__device__ float g_srcP2[NNODES];
__device__ float g_srcQ2[NNODES];
__device__ float g_dstP2[NNODES];
__device__ float g_dstQ2[NNODES];
__device__ float g_pnum[2 * NNODES * 256];    // partial numerators
__device__ float g_pden[8 * NNODES];          // [z][H][N]
__device__ uint32_t g_mask[NNODES * 128];     // adjacency bitmask
__device__ uint4 g_whF1[4 * 64 * 512];        // f16 frag tensor L1: [H][c64][4ks][4ntp][32lane] uint4
__device__ uint4 g_whF2[64 * 512];            // f16 frag tensor L2

// ---------------- helpers ------------------------------------------------------
__device__ __forceinline__ uint32_t pack_f16x2(float lo, float hi) {
    uint32_t r; asm("cvt.rn.f16x2.f32 %0, %1, %2;" : "=r"(r) : "f"(hi), "f"(lo)); return r;
}
__device__ __forceinline__ uint32_t hadd2(uint32_t a, uint32_t b) {
    uint32_t r; asm("add.rn.f16x2 %0, %1, %2;" : "=r"(r) : "r"(a), "r"(b)); return r;
}
__device__ __forceinline__ uint32_t hmax2(uint32_t a, uint32_t b) {
    uint32_t r; asm("max.f16x2 %0, %1, %2;" : "=r"(r) : "r"(a), "r"(b)); return r;
}
__device__ __forceinline__ uint32_t hex2(uint32_t a) {
    uint32_t r; asm("ex2.approx.f16x2 %0, %1;" : "=r"(r) : "r"(a)); return r;
}
__device__ __forceinline__ uint32_t prmt(uint32_t a, uint32_t b, uint32_t sel) {
    uint32_t r; asm("prmt.b32 %0, %1, %2, %3;" : "=r"(r) : "r"(a), "r"(b), "r"(sel)); return r;
}
__device__ __forceinline__ void mma_f16(float* c,
                                        uint32_t a0, uint32_t a1, uint32_t a2, uint32_t a3,
                                        uint32_t b0, uint32_t b1) {
    asm volatile(
        "mma.sync.aligned.m16n8k16.row.col.f32.f16.f16.f32 "
        "{%0,%1,%2,%3}, {%4,%5,%6,%7}, {%8,%9}, {%0,%1,%2,%3};"
        : "+f"(c[0]), "+f"(c[1]), "+f"(c[2]), "+f"(c[3])
        : "r"(a0), "r"(a1), "r"(a2), "r"(a3), "r"(b0), "r"(b1));
}
__device__ __forceinline__ void cp16(void* dst, const void* src) {
    uint32_t d = (uint32_t)__cvta_generic_to_shared(dst);
    asm volatile("cp.async.cg.shared.global [%0], [%1], 16;" :: "r"(d), "l"(src));
}
#define CP_COMMIT() asm volatile("cp.async.commit_group;" ::: "memory")
#define CP_WAIT(n)  asm volatile("cp.async.wait_group %0;" :: "n"(n) : "memory")
#define ONES_F16X2  0x3C003C00u

// ---------------- fused: gemm (blocks < ngemm) + adjacency pack (rest) --------
// gemm role: Y = X@W + B (fp32) and paired f16 fragment tensor YF.
// pack role: adj int32 -> bitmask (warp per row).
__global__ void __launch_bounds__(256) fused_gemm_pack_kernel(
    const float* __restrict__ X, const float* __restrict__ W,
    const float* __restrict__ B, float* __restrict__ Y, uint4* __restrict__ YF,
    const int* __restrict__ adj, uint32_t* __restrict__ maskb, int ngemm)
{
    const int bx = blockIdx.x;
    const int t  = threadIdx.x;

    if (bx >= ngemm) {
        // ---- pack role ----
        const int warp = t >> 5, lane = t & 31;
        const int r = (bx - ngemm) * 8 + warp;
        const int* row = adj + (size_t)r * NNODES;
        #pragma unroll
        for (int wg = 0; wg < 4; wg++) {
            uint32_t kept = 0;
            #pragma unroll
            for (int ww = 0; ww < 32; ww++) {
                int v = row[(wg * 32 + ww) * 32 + lane];
                uint32_t b = __ballot_sync(0xffffffffu, v > 0);
                if (lane == ww) kept = b;
            }
            maskb[(size_t)r * 128 + wg * 32 + lane] = kept;
        }
        return;
    }

    // ---- gemm role ----
    const int h  = bx >> 6;
    const int i0 = (bx & 63) * 64;
    const int dg = t & 15;
    const int ig = t >> 4;

    __shared__ float Xs[2][64][16];
    __shared__ float Ws[2][16][64];

    const float* Wh = W + (size_t)h * INDIM * HID;
    const int xrow = t >> 2, xseg = t & 3;
    const int wrow = t >> 4, wseg = t & 15;

    auto stage = [&](int buf, int kc) {
        cp16(&Xs[buf][xrow][xseg * 4], X + (size_t)(i0 + xrow) * INDIM + kc + xseg * 4);
        cp16(&Ws[buf][wrow][wseg * 4], Wh + (size_t)(kc + wrow) * HID + wseg * 4);
    };

    stage(0, 0);
    CP_COMMIT();

    float acc[4][4] = {};
    for (int kk = 0; kk < INDIM / 16; kk++) {
        if (kk + 1 < INDIM / 16) {
            stage((kk + 1) & 1, (kk + 1) * 16);
            CP_COMMIT();
            CP_WAIT(1);
        } else {
            CP_WAIT(0);
        }
        __syncthreads();
        const int buf = kk & 1;
        #pragma unroll
        for (int k = 0; k < 16; k++) {
            float4 wv = *(const float4*)(&Ws[buf][k][dg * 4]);
            float x0 = Xs[buf][ig * 4 + 0][k];
            float x1 = Xs[buf][ig * 4 + 1][k];
            float x2 = Xs[buf][ig * 4 + 2][k];
            float x3 = Xs[buf][ig * 4 + 3][k];
            acc[0][0] += x0 * wv.x; acc[0][1] += x0 * wv.y; acc[0][2] += x0 * wv.z; acc[0][3] += x0 * wv.w;
            acc[1][0] += x1 * wv.x; acc[1][1] += x1 * wv.y; acc[1][2] += x1 * wv.z; acc[1][3] += x1 * wv.w;
            acc[2][0] += x2 * wv.x; acc[2][1] += x2 * wv.y; acc[2][2] += x2 * wv.z; acc[2][3] += x2 * wv.w;
            acc[3][0] += x3 * wv.x; acc[3][1] += x3 * wv.y; acc[3][2] += x3 * wv.z; acc[3][3] += x3 * wv.w;
        }
        __syncthreads();
    }

    float4 bv = *(const float4*)(B + h * HID + dg * 4);
    float bb[4] = {bv.x, bv.y, bv.z, bv.w};
    #pragma unroll
    for (int ii = 0; ii < 4; ii++) {
        float4 r;
        r.x = acc[ii][0] + bb[0];
        r.y = acc[ii][1] + bb[1];
        r.z = acc[ii][2] + bb[2];
        r.w = acc[ii][3] + bb[3];
        *(float4*)(Y + ((size_t)h * NNODES + i0 + ig * 4 + ii) * HID + dg * 4) = r;
    }
    // paired f16 fragment tensor: [h][c64][ks][ntp][lane] uint4
    uint32_t* fb = (uint32_t*)(YF + (size_t)h * 64 * 512);
    #pragma unroll
    for (int c = 0; c < 4; c++) {
        const int d = dg * 4 + c;
        const int ntp = d >> 4;
        const int sub = (d >> 3) & 1;
        const int lnb = (d & 7) * 4;
        #pragma unroll
        for (int p = 0; p < 2; p++) {
            const int jp = i0 + ig * 4 + 2 * p;
            const int c64 = jp >> 6;
            const int ks = (jp >> 4) & 3;
            const int rr = jp & 15;
            const int lanei = lnb + ((rr & 7) >> 1);
            const int word = sub * 2 + (rr >> 3);
            uint32_t val = pack_f16x2(acc[2 * p][c] + bb[c], acc[2 * p + 1][c] + bb[c]);
            size_t idx = (((size_t)c64 * 4 + ks) * 4 + ntp) * 32 + lanei;
            fb[idx * 4 + word] = val;
        }
    }
}

// ---------------- src/dst projections (leaky pre-factored, log2e, shifted) ----
__global__ void srcdst_kernel(const float* __restrict__ wh,
                              const float* __restrict__ asrc,
                              const float* __restrict__ adst,
                              const float* __restrict__ ab,
                              float* __restrict__ osrcP, float* __restrict__ osrcQ,
                              float* __restrict__ odstP, float* __restrict__ odstQ,
                              int total)
{
    int gw = (blockIdx.x * blockDim.x + threadIdx.x) >> 5;
    int lane = threadIdx.x & 31;
    if (gw >= total) return;
    int h = gw >> 12;
    const float* row = wh + (size_t)gw * HID;
    float v0 = row[lane], v1 = row[lane + 32];
    float s = v0 * asrc[h * HID + lane] + v1 * asrc[h * HID + lane + 32];
    float d = v0 * adst[h * HID + lane] + v1 * adst[h * HID + lane + 32];
    #pragma unroll
    for (int o = 16; o > 0; o >>= 1) {
        s += __shfl_xor_sync(0xffffffffu, s, o);
        d += __shfl_xor_sync(0xffffffffu, d, o);
    }
    if (lane == 0) {
        float u = (s + ab[h]) * LOG2E;
        float v = d * LOG2E;
        osrcP[gw] = u - SHIFT;
        osrcQ[gw] = 0.2f * u - SHIFT;
        odstP[gw] = v;
        odstQ[gw] = 0.2f * v;
    }
}

// ---------------- fused attention: 64-j chunks, f16x2 scores, mma f16 ---------
__global__ void __launch_bounds__(256, 2) attn_mma_kernel(
    const uint4* __restrict__ whF,      // [H][64][4][4][32] uint4
    const float* __restrict__ srcP, const float* __restrict__ srcQ,  // [H][N]
    const float* __restrict__ dstP, const float* __restrict__ dstQ,  // [H][N]
    const uint32_t* __restrict__ maskb, // [N][128]
    float* __restrict__ pnum,           // [z][N][pcols]
    float* __restrict__ pden,           // [z][H][N]
    int pcols, int nheads)
{
    __shared__ alignas(16) uint4 bfragq[3][4][4][32];  // 3-stage, 8KB each
    __shared__ uint2 dsts2[1024];                      // (dstP2, dstQ2) per j-pair

    const int h    = blockIdx.y;
    const int t    = threadIdx.x;
    const int lane = t & 31;
    const int warp = t >> 5;
    const int gid  = lane >> 2;
    const int tig  = lane & 3;
    const int i0   = blockIdx.x * 128;
    const int z       = blockIdx.z;
    const int jsplit  = gridDim.z;
    const int nchunks = (NNODES / 64) / jsplit;
    const int jc0     = z * nchunks * 64;

    const int hN = h * NNODES;
    // stage dst pairs once (packed f16x2)
    for (int q = t; q < nchunks * 32; q += 256) {
        int j = jc0 + 2 * q;
        uint2 v;
        v.x = pack_f16x2(dstP[hN + j], dstP[hN + j + 1]);
        v.y = pack_f16x2(dstQ[hN + j], dstQ[hN + j + 1]);
        dsts2[q] = v;
    }

    const int iA = i0 + warp * 16 + gid;
    const int iB = iA + 8;
    const uint32_t srcP2A = pack_f16x2(srcP[hN + iA], srcP[hN + iA]);
    const uint32_t srcQ2A = pack_f16x2(srcQ[hN + iA], srcQ[hN + iA]);
    const uint32_t srcP2B = pack_f16x2(srcP[hN + iB], srcP[hN + iB]);
    const uint32_t srcQ2B = pack_f16x2(srcQ[hN + iB], srcQ[hN + iB]);
    const uint2* mA2 = (const uint2*)(maskb + (size_t)iA * 128 + (jc0 >> 5));
    const uint2* mB2 = (const uint2*)(maskb + (size_t)iB * 128 + (jc0 >> 5));

    const uint4* gsrc = whF + ((size_t)h * 64 + (jc0 >> 6)) * 512;

    float acc[9][4];
    #pragma unroll
    for (int n = 0; n < 9; n++)
        #pragma unroll
        for (int r = 0; r < 4; r++) acc[n][r] = 0.f;

    // prologue: stage chunks 0,1 (512 uint4 each = 2 cp16/thread)
    {
        uint4* d0 = &bfragq[0][0][0][0];
        cp16(d0 + t, gsrc + t);
        cp16(d0 + t + 256, gsrc + t + 256);
        CP_COMMIT();
        uint4* d1 = &bfragq[1][0][0][0];
        cp16(d1 + t, gsrc + 512 + t);
        cp16(d1 + t + 256, gsrc + 512 + t + 256);
        CP_COMMIT();
    }

    const int tshift = 2 * tig;
    int buf = 0, nbuf = 2;
    for (int chunk = 0; chunk < nchunks; chunk++) {
        const uint2 wAu = mA2[chunk];
        const uint2 wBu = mB2[chunk];

        CP_WAIT(1);
        __syncthreads();
        if (chunk + 2 < nchunks) {
            uint4* dn = &bfragq[nbuf][0][0][0];
            const uint4* sn = gsrc + (size_t)(chunk + 2) * 512;
            cp16(dn + t, sn + t);
            cp16(dn + t + 256, sn + t + 256);
        }
        CP_COMMIT();

        #pragma unroll
        for (int ks = 0; ks < 4; ks++) {
            uint32_t pAm = ((ks < 2) ? wAu.x : wAu.y) >> ((ks & 1) * 16 + tshift);
            uint32_t pBm = ((ks < 2) ? wBu.x : wBu.y) >> ((ks & 1) * 16 + tshift);
            // sign-replicate mask expansion: bits {0,1,8,9} -> halfword masks
            uint32_t sA1 = pAm << 7,  sA2 = pAm << 14;
            uint32_t sB1 = pBm << 7,  sB2 = pBm << 14;
            uint32_t mskA0 = prmt(sA1, sA2, 0xDD88u);
            uint32_t mskA1 = prmt(sA1, sA2, 0xEE99u);
            uint32_t mskB0 = prmt(sB1, sB2, 0xDD88u);
            uint32_t mskB1 = prmt(sB1, sB2, 0xEE99u);

            const int pidx = chunk * 32 + ks * 8 + tig;
            uint2 dd0 = dsts2[pidx];       // j pair (2tig, 2tig+1)
            uint2 dd1 = dsts2[pidx + 4];   // j pair (2tig+8, 2tig+9)

            uint32_t eA0 = hex2(hmax2(hadd2(srcP2A, dd0.x), hadd2(srcQ2A, dd0.y))) & mskA0;
            uint32_t eA1 = hex2(hmax2(hadd2(srcP2A, dd1.x), hadd2(srcQ2A, dd1.y))) & mskA1;
            uint32_t eB0 = hex2(hmax2(hadd2(srcP2B, dd0.x), hadd2(srcQ2B, dd0.y))) & mskB0;
            uint32_t eB1 = hex2(hmax2(hadd2(srcP2B, dd1.x), hadd2(srcQ2B, dd1.y))) & mskB1;

            const uint4* bk = &bfragq[buf][ks][0][lane];
            #pragma unroll
            for (int ntp = 0; ntp < 4; ntp++) {
                uint4 b = bk[ntp * 32];
                mma_f16(acc[2 * ntp],     eA0, eB0, eA1, eB1, b.x, b.y);
                mma_f16(acc[2 * ntp + 1], eA0, eB0, eA1, eB1, b.z, b.w);
            }
            mma_f16(acc[8], eA0, eB0, eA1, eB1, ONES_F16X2, ONES_F16X2);
        }

        buf  = (buf == 2)  ? 0 : buf + 1;
        nbuf = (nbuf == 2) ? 0 : nbuf + 1;
    }

    const float denA = acc[8][0];   // ones-column: row gid
    const float denB = acc[8][2];   // ones-column: row gid+8

    float* pA = pnum + ((size_t)z * NNODES + iA) * pcols + h * 64 + 2 * tig;
    float* pB = pnum + ((size_t)z * NNODES + iB) * pcols + h * 64 + 2 * tig;
    #pragma unroll
    for (int nt = 0; nt < 8; nt++) {
        float2 va, vb;
        va.x = acc[nt][0]; va.y = acc[nt][1];
        vb.x = acc[nt][2]; vb.y = acc[nt][3];
        *(float2*)(pA + nt * 8) = va;
        *(float2*)(pB + nt * 8) = vb;
    }
    if (tig == 0) {
        pden[((size_t)z * nheads + h) * NNODES + iA] = denA;
        pden[((size_t)z * nheads + h) * NNODES + iB] = denB;
    }
}

// ---------------- partial reduce + softmax divide + elu -----------------------
__global__ void reduce_kernel(const float* __restrict__ pnum,
                              const float* __restrict__ pden,
                              float* __restrict__ out,
                              int zn, int cols, int cqs, int H)
{
    int idx = blockIdx.x * blockDim.x + threadIdx.x;
    int i = idx >> cqs;
    int c = (idx & ((1 << cqs) - 1)) << 2;
    int h = c >> 6;
    float den = 0.f;
    for (int zz = 0; zz < zn; zz++)
        den += pden[((size_t)zz * H + h) * NNODES + i];
    float4 a = *(const float4*)(pnum + ((size_t)i) * cols + c);
    for (int zz = 1; zz < zn; zz++) {
        float4 b = *(const float4*)(pnum + ((size_t)zz * NNODES + i) * cols + c);
        a.x += b.x; a.y += b.y; a.z += b.z; a.w += b.w;
    }
    float inv = 1.f / den;
    float v[4] = {a.x * inv, a.y * inv, a.z * inv, a.w * inv};
    #pragma unroll
    for (int r = 0; r < 4; r++) v[r] = (v[r] > 0.f) ? v[r] : expm1f(v[r]);
    float4 o4; o4.x = v[0]; o4.y = v[1]; o4.z = v[2]; o4.w = v[3];
    *(float4*)(out + (size_t)i * cols + c) = o4;
}

// ---------------- launch ------------------------------------------------------
extern "C" void kernel_launch(void* const* d_in, const int* in_sizes, int n_in,
                              void* d_out, int out_size)
{
    const float* h      = (const float*)d_in[0];
    const int*   adj    = (const int*)  d_in[1];
    const float* Wh     = (const float*)d_in[2];
    const float* bWh    = (const float*)d_in[3];
    const float* a_src  = (const float*)d_in[4];
    const float* a_dst  = (const float*)d_in[5];
    const float* a_b    = (const float*)d_in[6];
    const float* Wo     = (const float*)d_in[7];
    const float* bWo    = (const float*)d_in[8];
    const float* ao_src = (const float*)d_in[9];
    const float* ao_dst = (const float*)d_in[10];
    const float* ao_b   = (const float*)d_in[11];
    float* out = (float*)d_out;

    float *wh1, *x2, *wh2, *pnum, *pden;
    float *sP1, *sQ1, *dP1, *dQ1, *sP2, *sQ2, *dP2, *dQ2;
    uint32_t* maskb;
    uint4 *whF1, *whF2;
    cudaGetSymbolAddress((void**)&wh1,  g_wh1);
    cudaGetSymbolAddress((void**)&x2,   g_x2);
    cudaGetSymbolAddress((void**)&wh2,  g_wh2);
    cudaGetSymbolAddress((void**)&sP1, g_srcP1);
    cudaGetSymbolAddress((void**)&sQ1, g_srcQ1);
    cudaGetSymbolAddress((void**)&dP1, g_dstP1);
    cudaGetSymbolAddress((void**)&dQ1, g_dstQ1);
    cudaGetSymbolAddress((void**)&sP2, g_srcP2);
    cudaGetSymbolAddress((void**)&sQ2, g_srcQ2);
    cudaGetSymbolAddress((void**)&dP2, g_dstP2);
    cudaGetSymbolAddress((void**)&dQ2, g_dstQ2);
    cudaGetSymbolAddress((void**)&pnum, g_pnum);
    cudaGetSymbolAddress((void**)&pden, g_pden);
    cudaGetSymbolAddress((void**)&maskb, g_mask);
    cudaGetSymbolAddress((void**)&whF1, g_whF1);
    cudaGetSymbolAddress((void**)&whF2, g_whF2);

    // Layer 1: gemm (256 blocks) + pack (512 blocks) fused in one launch
    fused_gemm_pack_kernel<<<256 + 512, 256>>>(h, Wh, bWh, wh1, whF1, adj, maskb, 256);
    srcdst_kernel<<<4 * 512, 256>>>(wh1, a_src, a_dst, a_b, sP1, sQ1, dP1, dQ1, 4 * NNODES);
    attn_mma_kernel<<<dim3(NNODES / 128, 4, 2), 256>>>(whF1, sP1, sQ1, dP1, dQ1, maskb, pnum, pden, 256, 4);
    reduce_kernel<<<(NNODES * 64) / 256, 256>>>(pnum, pden, x2, 2, 256, 6, 4);

    // Layer 2 (jsplit=8)
    fused_gemm_pack_kernel<<<64, 256>>>(x2, Wo, bWo, wh2, whF2, adj, maskb, 64);
    srcdst_kernel<<<512, 256>>>(wh2, ao_src, ao_dst, ao_b, sP2, sQ2, dP2, dQ2, NNODES);
    attn_mma_kernel<<<dim3(NNODES / 128, 1, 8), 256>>>(whF2, sP2, sQ2, dP2, dQ2, maskb, pnum, pden, 64, 1);
    reduce_kernel<<<(NNODES * 16) / 256, 256>>>(pnum, pden, out, 8, 64, 4, 1);
}

// round 10
// speedup vs baseline: 8.4828x; 1.0530x over previous
#include <cuda_runtime.h>
#include <cstdint>
#include <cstddef>

#define NNODES 4096
#define INDIM 256
#define HID 64
#define LOG2E 1.4426950408889634f
#define SHIFT 4.0f

// ---------------- scratch (no allocation allowed) ----------------
__device__ float g_x2[NNODES * 256];          // concat heads [N][256]
__device__ float g_srcP1[4 * NNODES];
__device__ float g_srcQ1[4 * NNODES];
__device__ float g_dstP1[4 * NNODES];
__device__ float g_dstQ1[4 * NNODES];
__device__ float g_srcP2[NNODES];
__device__ float g_srcQ2[NNODES];
__device__ float g_dstP2[NNODES];
__device__ float g_dstQ2[NNODES];
__device__ float g_pnum[2 * NNODES * 256];    // partial numerators
__device__ float g_pden[8 * NNODES];          // [z][H][N]
__device__ uint32_t g_mask[NNODES * 128];     // adjacency bitmask
__device__ uint4 g_whF1[4 * 64 * 512];        // f16 frag tensor L1: [H][c64][4ks][4ntp][32lane] uint4
__device__ uint4 g_whF2[64 * 512];            // f16 frag tensor L2

// ---------------- helpers ------------------------------------------------------
__device__ __forceinline__ uint32_t pack_f16x2(float lo, float hi) {
    uint32_t r; asm("cvt.rn.f16x2.f32 %0, %1, %2;" : "=r"(r) : "f"(hi), "f"(lo)); return r;
}
__device__ __forceinline__ uint32_t hadd2(uint32_t a, uint32_t b) {
    uint32_t r; asm("add.rn.f16x2 %0, %1, %2;" : "=r"(r) : "r"(a), "r"(b)); return r;
}
__device__ __forceinline__ uint32_t hmax2(uint32_t a, uint32_t b) {
    uint32_t r; asm("max.f16x2 %0, %1, %2;" : "=r"(r) : "r"(a), "r"(b)); return r;
}
__device__ __forceinline__ uint32_t hex2(uint32_t a) {
    uint32_t r; asm("ex2.approx.f16x2 %0, %1;" : "=r"(r) : "r"(a)); return r;
}
__device__ __forceinline__ uint32_t prmt(uint32_t a, uint32_t b, uint32_t sel) {
    uint32_t r; asm("prmt.b32 %0, %1, %2, %3;" : "=r"(r) : "r"(a), "r"(b), "r"(sel)); return r;
}
__device__ __forceinline__ void mma_f16(float* c,
                                        uint32_t a0, uint32_t a1, uint32_t a2, uint32_t a3,
                                        uint32_t b0, uint32_t b1) {
    asm volatile(
        "mma.sync.aligned.m16n8k16.row.col.f32.f16.f16.f32 "
        "{%0,%1,%2,%3}, {%4,%5,%6,%7}, {%8,%9}, {%0,%1,%2,%3};"
        : "+f"(c[0]), "+f"(c[1]), "+f"(c[2]), "+f"(c[3])
        : "r"(a0), "r"(a1), "r"(a2), "r"(a3), "r"(b0), "r"(b1));
}
__device__ __forceinline__ void cp16(void* dst, const void* src) {
    uint32_t d = (uint32_t)__cvta_generic_to_shared(dst);
    asm volatile("cp.async.cg.shared.global [%0], [%1], 16;" :: "r"(d), "l"(src));
}
#define CP_COMMIT() asm volatile("cp.async.commit_group;" ::: "memory")
#define CP_WAIT(n)  asm volatile("cp.async.wait_group %0;" :: "n"(n) : "memory")
#define ONES_F16X2  0x3C003C00u

// ---------------- fused: gemm+srcdst (blocks < ngemm) + adjacency pack --------
// gemm role: frag tensor YF (f16, bias folded) + src/dst projection vectors.
// pack role: adj int32 -> bitmask (warp per row).
__global__ void __launch_bounds__(256) fused_gemm_pack_kernel(
    const float* __restrict__ X, const float* __restrict__ W,
    const float* __restrict__ B, uint4* __restrict__ YF,
    const float* __restrict__ Asrc, const float* __restrict__ Adst,
    const float* __restrict__ Ab,
    float* __restrict__ srcP, float* __restrict__ srcQ,
    float* __restrict__ dstP, float* __restrict__ dstQ,
    const int* __restrict__ adj, uint32_t* __restrict__ maskb, int ngemm)
{
    const int bx = blockIdx.x;
    const int t  = threadIdx.x;

    if (bx >= ngemm) {
        // ---- pack role ----
        const int warp = t >> 5, lane = t & 31;
        const int r = (bx - ngemm) * 8 + warp;
        const int* row = adj + (size_t)r * NNODES;
        #pragma unroll
        for (int wg = 0; wg < 4; wg++) {
            uint32_t kept = 0;
            #pragma unroll
            for (int ww = 0; ww < 32; ww++) {
                int v = row[(wg * 32 + ww) * 32 + lane];
                uint32_t b = __ballot_sync(0xffffffffu, v > 0);
                if (lane == ww) kept = b;
            }
            maskb[(size_t)r * 128 + wg * 32 + lane] = kept;
        }
        return;
    }

    // ---- gemm role ----
    const int h  = bx >> 6;
    const int i0 = (bx & 63) * 64;
    const int dg = t & 15;
    const int ig = t >> 4;

    __shared__ float Xs[2][64][16];
    __shared__ float Ws[2][16][64];

    const float* Wh = W + (size_t)h * INDIM * HID;
    const int xrow = t >> 2, xseg = t & 3;
    const int wrow = t >> 4, wseg = t & 15;

    auto stage = [&](int buf, int kc) {
        cp16(&Xs[buf][xrow][xseg * 4], X + (size_t)(i0 + xrow) * INDIM + kc + xseg * 4);
        cp16(&Ws[buf][wrow][wseg * 4], Wh + (size_t)(kc + wrow) * HID + wseg * 4);
    };

    stage(0, 0);
    CP_COMMIT();

    float acc[4][4] = {};
    for (int kk = 0; kk < INDIM / 16; kk++) {
        if (kk + 1 < INDIM / 16) {
            stage((kk + 1) & 1, (kk + 1) * 16);
            CP_COMMIT();
            CP_WAIT(1);
        } else {
            CP_WAIT(0);
        }
        __syncthreads();
        const int buf = kk & 1;
        #pragma unroll
        for (int k = 0; k < 16; k++) {
            float4 wv = *(const float4*)(&Ws[buf][k][dg * 4]);
            float x0 = Xs[buf][ig * 4 + 0][k];
            float x1 = Xs[buf][ig * 4 + 1][k];
            float x2 = Xs[buf][ig * 4 + 2][k];
            float x3 = Xs[buf][ig * 4 + 3][k];
            acc[0][0] += x0 * wv.x; acc[0][1] += x0 * wv.y; acc[0][2] += x0 * wv.z; acc[0][3] += x0 * wv.w;
            acc[1][0] += x1 * wv.x; acc[1][1] += x1 * wv.y; acc[1][2] += x1 * wv.z; acc[1][3] += x1 * wv.w;
            acc[2][0] += x2 * wv.x; acc[2][1] += x2 * wv.y; acc[2][2] += x2 * wv.z; acc[2][3] += x2 * wv.w;
            acc[3][0] += x3 * wv.x; acc[3][1] += x3 * wv.y; acc[3][2] += x3 * wv.z; acc[3][3] += x3 * wv.w;
        }
        __syncthreads();
    }

    // fold bias into acc
    float4 bv = *(const float4*)(B + h * HID + dg * 4);
    #pragma unroll
    for (int ii = 0; ii < 4; ii++) {
        acc[ii][0] += bv.x; acc[ii][1] += bv.y;
        acc[ii][2] += bv.z; acc[ii][3] += bv.w;
    }

    // src/dst projections: per-thread partial dot + 16-lane butterfly
    {
        float4 asv = *(const float4*)(Asrc + h * HID + dg * 4);
        float4 adv = *(const float4*)(Adst + h * HID + dg * 4);
        float sv[4], dvv[4];
        #pragma unroll
        for (int ii = 0; ii < 4; ii++) {
            sv[ii]  = acc[ii][0] * asv.x + acc[ii][1] * asv.y + acc[ii][2] * asv.z + acc[ii][3] * asv.w;
            dvv[ii] = acc[ii][0] * adv.x + acc[ii][1] * adv.y + acc[ii][2] * adv.z + acc[ii][3] * adv.w;
        }
        #pragma unroll
        for (int o = 1; o < 16; o <<= 1) {
            #pragma unroll
            for (int ii = 0; ii < 4; ii++) {
                sv[ii]  += __shfl_xor_sync(0xffffffffu, sv[ii], o);
                dvv[ii] += __shfl_xor_sync(0xffffffffu, dvv[ii], o);
            }
        }
        if (dg == 0) {
            const float abh = Ab[h];
            #pragma unroll
            for (int ii = 0; ii < 4; ii++) {
                const int gi = h * NNODES + i0 + ig * 4 + ii;
                float u = (sv[ii] + abh) * LOG2E;
                float v = dvv[ii] * LOG2E;
                srcP[gi] = u - SHIFT;
                srcQ[gi] = 0.2f * u - SHIFT;
                dstP[gi] = v;
                dstQ[gi] = 0.2f * v;
            }
        }
    }

    // paired f16 fragment tensor: [h][c64][ks][ntp][lane] uint4 (bias already in acc)
    uint32_t* fb = (uint32_t*)(YF + (size_t)h * 64 * 512);
    #pragma unroll
    for (int c = 0; c < 4; c++) {
        const int d = dg * 4 + c;
        const int ntp = d >> 4;
        const int sub = (d >> 3) & 1;
        const int lnb = (d & 7) * 4;
        #pragma unroll
        for (int p = 0; p < 2; p++) {
            const int jp = i0 + ig * 4 + 2 * p;
            const int c64 = jp >> 6;
            const int ks = (jp >> 4) & 3;
            const int rr = jp & 15;
            const int lanei = lnb + ((rr & 7) >> 1);
            const int word = sub * 2 + (rr >> 3);
            uint32_t val = pack_f16x2(acc[2 * p][c], acc[2 * p + 1][c]);
            size_t idx = (((size_t)c64 * 4 + ks) * 4 + ntp) * 32 + lanei;
            fb[idx * 4 + word] = val;
        }
    }
}

// ---------------- fused attention: 64-j chunks, f16x2 scores, mma f16 ---------
__global__ void __launch_bounds__(256, 2) attn_mma_kernel(
    const uint4* __restrict__ whF,      // [H][64][4][4][32] uint4
    const float* __restrict__ srcP, const float* __restrict__ srcQ,  // [H][N]
    const float* __restrict__ dstP, const float* __restrict__ dstQ,  // [H][N]
    const uint32_t* __restrict__ maskb, // [N][128]
    float* __restrict__ pnum,           // [z][N][pcols]
    float* __restrict__ pden,           // [z][H][N]
    int pcols, int nheads)
{
    __shared__ alignas(16) uint4 bfragq[3][4][4][32];  // 3-stage, 8KB each
    __shared__ uint2 dsts2[1024];                      // (dstP2, dstQ2) per j-pair

    const int h    = blockIdx.y;
    const int t    = threadIdx.x;
    const int lane = t & 31;
    const int warp = t >> 5;
    const int gid  = lane >> 2;
    const int tig  = lane & 3;
    const int i0   = blockIdx.x * 128;
    const int z       = blockIdx.z;
    const int jsplit  = gridDim.z;
    const int nchunks = (NNODES / 64) / jsplit;
    const int jc0     = z * nchunks * 64;

    const int hN = h * NNODES;
    // stage dst pairs once (packed f16x2)
    for (int q = t; q < nchunks * 32; q += 256) {
        int j = jc0 + 2 * q;
        uint2 v;
        v.x = pack_f16x2(dstP[hN + j], dstP[hN + j + 1]);
        v.y = pack_f16x2(dstQ[hN + j], dstQ[hN + j + 1]);
        dsts2[q] = v;
    }

    const int iA = i0 + warp * 16 + gid;
    const int iB = iA + 8;
    const uint32_t srcP2A = pack_f16x2(srcP[hN + iA], srcP[hN + iA]);
    const uint32_t srcQ2A = pack_f16x2(srcQ[hN + iA], srcQ[hN + iA]);
    const uint32_t srcP2B = pack_f16x2(srcP[hN + iB], srcP[hN + iB]);
    const uint32_t srcQ2B = pack_f16x2(srcQ[hN + iB], srcQ[hN + iB]);
    const uint2* mA2 = (const uint2*)(maskb + (size_t)iA * 128 + (jc0 >> 5));
    const uint2* mB2 = (const uint2*)(maskb + (size_t)iB * 128 + (jc0 >> 5));

    const uint4* gsrc = whF + ((size_t)h * 64 + (jc0 >> 6)) * 512;

    float acc[9][4];
    #pragma unroll
    for (int n = 0; n < 9; n++)
        #pragma unroll
        for (int r = 0; r < 4; r++) acc[n][r] = 0.f;

    // prologue: stage chunks 0,1 (512 uint4 each = 2 cp16/thread)
    {
        uint4* d0 = &bfragq[0][0][0][0];
        cp16(d0 + t, gsrc + t);
        cp16(d0 + t + 256, gsrc + t + 256);
        CP_COMMIT();
        uint4* d1 = &bfragq[1][0][0][0];
        cp16(d1 + t, gsrc + 512 + t);
        cp16(d1 + t + 256, gsrc + 512 + t + 256);
        CP_COMMIT();
    }

    const int tshift = 2 * tig;
    int buf = 0, nbuf = 2;
    for (int chunk = 0; chunk < nchunks; chunk++) {
        const uint2 wAu = mA2[chunk];
        const uint2 wBu = mB2[chunk];

        CP_WAIT(1);
        __syncthreads();
        if (chunk + 2 < nchunks) {
            uint4* dn = &bfragq[nbuf][0][0][0];
            const uint4* sn = gsrc + (size_t)(chunk + 2) * 512;
            cp16(dn + t, sn + t);
            cp16(dn + t + 256, sn + t + 256);
        }
        CP_COMMIT();

        #pragma unroll
        for (int ks = 0; ks < 4; ks++) {
            uint32_t pAm = ((ks < 2) ? wAu.x : wAu.y) >> ((ks & 1) * 16 + tshift);
            uint32_t pBm = ((ks < 2) ? wBu.x : wBu.y) >> ((ks & 1) * 16 + tshift);
            // sign-replicate mask expansion: bits {0,1,8,9} -> halfword masks
            uint32_t sA1 = pAm << 7,  sA2 = pAm << 14;
            uint32_t sB1 = pBm << 7,  sB2 = pBm << 14;
            uint32_t mskA0 = prmt(sA1, sA2, 0xDD88u);
            uint32_t mskA1 = prmt(sA1, sA2, 0xEE99u);
            uint32_t mskB0 = prmt(sB1, sB2, 0xDD88u);
            uint32_t mskB1 = prmt(sB1, sB2, 0xEE99u);

            const int pidx = chunk * 32 + ks * 8 + tig;
            uint2 dd0 = dsts2[pidx];       // j pair (2tig, 2tig+1)
            uint2 dd1 = dsts2[pidx + 4];   // j pair (2tig+8, 2tig+9)

            uint32_t eA0 = hex2(hmax2(hadd2(srcP2A, dd0.x), hadd2(srcQ2A, dd0.y))) & mskA0;
            uint32_t eA1 = hex2(hmax2(hadd2(srcP2A, dd1.x), hadd2(srcQ2A, dd1.y))) & mskA1;
            uint32_t eB0 = hex2(hmax2(hadd2(srcP2B, dd0.x), hadd2(srcQ2B, dd0.y))) & mskB0;
            uint32_t eB1 = hex2(hmax2(hadd2(srcP2B, dd1.x), hadd2(srcQ2B, dd1.y))) & mskB1;

            const uint4* bk = &bfragq[buf][ks][0][lane];
            #pragma unroll
            for (int ntp = 0; ntp < 4; ntp++) {
                uint4 b = bk[ntp * 32];
                mma_f16(acc[2 * ntp],     eA0, eB0, eA1, eB1, b.x, b.y);
                mma_f16(acc[2 * ntp + 1], eA0, eB0, eA1, eB1, b.z, b.w);
            }
            mma_f16(acc[8], eA0, eB0, eA1, eB1, ONES_F16X2, ONES_F16X2);
        }

        buf  = (buf == 2)  ? 0 : buf + 1;
        nbuf = (nbuf == 2) ? 0 : nbuf + 1;
    }

    const float denA = acc[8][0];   // ones-column: row gid
    const float denB = acc[8][2];   // ones-column: row gid+8

    float* pA = pnum + ((size_t)z * NNODES + iA) * pcols + h * 64 + 2 * tig;
    float* pB = pnum + ((size_t)z * NNODES + iB) * pcols + h * 64 + 2 * tig;
    #pragma unroll
    for (int nt = 0; nt < 8; nt++) {
        float2 va, vb;
        va.x = acc[nt][0]; va.y = acc[nt][1];
        vb.x = acc[nt][2]; vb.y = acc[nt][3];
        *(float2*)(pA + nt * 8) = va;
        *(float2*)(pB + nt * 8) = vb;
    }
    if (tig == 0) {
        pden[((size_t)z * nheads + h) * NNODES + iA] = denA;
        pden[((size_t)z * nheads + h) * NNODES + iB] = denB;
    }
}

// ---------------- partial reduce + softmax divide + elu (templated ILP) -------
template<int ZN, int COLS, int CSHIFT, int H>
__global__ void reduce_kernel(const float* __restrict__ pnum,
                              const float* __restrict__ pden,
                              float* __restrict__ out)
{
    int idx = blockIdx.x * blockDim.x + threadIdx.x;
    int i = idx >> CSHIFT;
    int c = (idx & ((1 << CSHIFT) - 1)) << 3;   // 8 cols per thread
    int h = c >> 6;

    float den = 0.f;
    #pragma unroll
    for (int zz = 0; zz < ZN; zz++)
        den += pden[((size_t)zz * H + h) * NNODES + i];

    float4 a0, a1;
    {
        const float* p = pnum + (size_t)i * COLS + c;
        a0 = *(const float4*)p;
        a1 = *(const float4*)(p + 4);
    }
    #pragma unroll
    for (int zz = 1; zz < ZN; zz++) {
        const float* p = pnum + ((size_t)zz * NNODES + i) * COLS + c;
        float4 b0 = *(const float4*)p;
        float4 b1 = *(const float4*)(p + 4);
        a0.x += b0.x; a0.y += b0.y; a0.z += b0.z; a0.w += b0.w;
        a1.x += b1.x; a1.y += b1.y; a1.z += b1.z; a1.w += b1.w;
    }
    float inv = 1.f / den;
    float v[8] = {a0.x * inv, a0.y * inv, a0.z * inv, a0.w * inv,
                  a1.x * inv, a1.y * inv, a1.z * inv, a1.w * inv};
    #pragma unroll
    for (int r = 0; r < 8; r++) v[r] = (v[r] > 0.f) ? v[r] : expm1f(v[r]);
    float4 o0 = {v[0], v[1], v[2], v[3]};
    float4 o1 = {v[4], v[5], v[6], v[7]};
    float* op = out + (size_t)i * COLS + c;
    *(float4*)op = o0;
    *(float4*)(op + 4) = o1;
}

// ---------------- launch ------------------------------------------------------
extern "C" void kernel_launch(void* const* d_in, const int* in_sizes, int n_in,
                              void* d_out, int out_size)
{
    const float* h      = (const float*)d_in[0];
    const int*   adj    = (const int*)  d_in[1];
    const float* Wh     = (const float*)d_in[2];
    const float* bWh    = (const float*)d_in[3];
    const float* a_src  = (const float*)d_in[4];
    const float* a_dst  = (const float*)d_in[5];
    const float* a_b    = (const float*)d_in[6];
    const float* Wo     = (const float*)d_in[7];
    const float* bWo    = (const float*)d_in[8];
    const float* ao_src = (const float*)d_in[9];
    const float* ao_dst = (const float*)d_in[10];
    const float* ao_b   = (const float*)d_in[11];
    float* out = (float*)d_out;

    float *x2, *pnum, *pden;
    float *sP1, *sQ1, *dP1, *dQ1, *sP2, *sQ2, *dP2, *dQ2;
    uint32_t* maskb;
    uint4 *whF1, *whF2;
    cudaGetSymbolAddress((void**)&x2,   g_x2);
    cudaGetSymbolAddress((void**)&sP1, g_srcP1);
    cudaGetSymbolAddress((void**)&sQ1, g_srcQ1);
    cudaGetSymbolAddress((void**)&dP1, g_dstP1);
    cudaGetSymbolAddress((void**)&dQ1, g_dstQ1);
    cudaGetSymbolAddress((void**)&sP2, g_srcP2);
    cudaGetSymbolAddress((void**)&sQ2, g_srcQ2);
    cudaGetSymbolAddress((void**)&dP2, g_dstP2);
    cudaGetSymbolAddress((void**)&dQ2, g_dstQ2);
    cudaGetSymbolAddress((void**)&pnum, g_pnum);
    cudaGetSymbolAddress((void**)&pden, g_pden);
    cudaGetSymbolAddress((void**)&maskb, g_mask);
    cudaGetSymbolAddress((void**)&whF1, g_whF1);
    cudaGetSymbolAddress((void**)&whF2, g_whF2);

    // Layer 1: gemm+srcdst (256 blocks) + pack (512 blocks) fused in one launch
    fused_gemm_pack_kernel<<<256 + 512, 256>>>(h, Wh, bWh, whF1,
                                               a_src, a_dst, a_b,
                                               sP1, sQ1, dP1, dQ1,
                                               adj, maskb, 256);
    attn_mma_kernel<<<dim3(NNODES / 128, 4, 2), 256>>>(whF1, sP1, sQ1, dP1, dQ1, maskb, pnum, pden, 256, 4);
    reduce_kernel<2, 256, 5, 4><<<(NNODES * 32) / 256, 256>>>(pnum, pden, x2);

    // Layer 2 (jsplit=8)
    fused_gemm_pack_kernel<<<64, 256>>>(x2, Wo, bWo, whF2,
                                        ao_src, ao_dst, ao_b,
                                        sP2, sQ2, dP2, dQ2,
                                        adj, maskb, 64);
    attn_mma_kernel<<<dim3(NNODES / 128, 1, 8), 256>>>(whF2, sP2, sQ2, dP2, dQ2, maskb, pnum, pden, 64, 1);
    reduce_kernel<8, 64, 3, 1><<<(NNODES * 8) / 256, 256>>>(pnum, pden, out);
}

// round 11
// speedup vs baseline: 9.1243x; 1.0756x over previous
#include <cuda_runtime.h>
#include <cstdint>
#include <cstddef>

#define NNODES 4096
#define INDIM 256
#define HID 64
#define LOG2E 1.4426950408889634f
#define SHIFT 4.0f

// ---------------- scratch (no allocation allowed) ----------------
__device__ float g_x2[NNODES * 256];          // concat heads [N][256]
__device__ float g_srcP1[4 * NNODES];
__device__ float g_srcQ1[4 * NNODES];
__device__ float g_dstP1[4 * NNODES];
__device__ float g_dstQ1[4 * NNODES];
__device__ float g_srcP2[NNODES];
__device__ float g_srcQ2[NNODES];
__device__ float g_dstP2[NNODES];
__device__ float g_dstQ2[NNODES];
__device__ float g_pnum[2 * NNODES * 256];    // partial numerators
__device__ float g_pden[8 * NNODES];          // [z][H][N]
__device__ uint32_t g_mask[NNODES * 128];     // adjacency bitmask
__device__ uint4 g_whF1[4 * 64 * 512];        // f16 frag tensor L1: [H][c64][4ks][4ntp][32lane] uint4
__device__ uint4 g_whF2[64 * 512];            // f16 frag tensor L2

// ---------------- helpers ------------------------------------------------------
__device__ __forceinline__ uint32_t pack_f16x2(float lo, float hi) {
    uint32_t r; asm("cvt.rn.f16x2.f32 %0, %1, %2;" : "=r"(r) : "f"(hi), "f"(lo)); return r;
}
__device__ __forceinline__ uint32_t hadd2(uint32_t a, uint32_t b) {
    uint32_t r; asm("add.rn.f16x2 %0, %1, %2;" : "=r"(r) : "r"(a), "r"(b)); return r;
}
__device__ __forceinline__ uint32_t hmax2(uint32_t a, uint32_t b) {
    uint32_t r; asm("max.f16x2 %0, %1, %2;" : "=r"(r) : "r"(a), "r"(b)); return r;
}
__device__ __forceinline__ uint32_t hex2(uint32_t a) {
    uint32_t r; asm("ex2.approx.f16x2 %0, %1;" : "=r"(r) : "r"(a)); return r;
}
__device__ __forceinline__ uint32_t prmt(uint32_t a, uint32_t b, uint32_t sel) {
    uint32_t r; asm("prmt.b32 %0, %1, %2, %3;" : "=r"(r) : "r"(a), "r"(b), "r"(sel)); return r;
}
__device__ __forceinline__ void mma_f16(float* c,
                                        uint32_t a0, uint32_t a1, uint32_t a2, uint32_t a3,
                                        uint32_t b0, uint32_t b1) {
    asm volatile(
        "mma.sync.aligned.m16n8k16.row.col.f32.f16.f16.f32 "
        "{%0,%1,%2,%3}, {%4,%5,%6,%7}, {%8,%9}, {%0,%1,%2,%3};"
        : "+f"(c[0]), "+f"(c[1]), "+f"(c[2]), "+f"(c[3])
        : "r"(a0), "r"(a1), "r"(a2), "r"(a3), "r"(b0), "r"(b1));
}
__device__ __forceinline__ void cp16(void* dst, const void* src) {
    uint32_t d = (uint32_t)__cvta_generic_to_shared(dst);
    asm volatile("cp.async.cg.shared.global [%0], [%1], 16;" :: "r"(d), "l"(src));
}
#define CP_COMMIT() asm volatile("cp.async.commit_group;" ::: "memory")
#define CP_WAIT(n)  asm volatile("cp.async.wait_group %0;" :: "n"(n) : "memory")
#define ONES_F16X2  0x3C003C00u

// ---------------- fused: gemm+srcdst (blocks < ngemm) + adjacency pack --------
__global__ void __launch_bounds__(256) fused_gemm_pack_kernel(
    const float* __restrict__ X, const float* __restrict__ W,
    const float* __restrict__ B, uint4* __restrict__ YF,
    const float* __restrict__ Asrc, const float* __restrict__ Adst,
    const float* __restrict__ Ab,
    float* __restrict__ srcP, float* __restrict__ srcQ,
    float* __restrict__ dstP, float* __restrict__ dstQ,
    const int* __restrict__ adj, uint32_t* __restrict__ maskb, int ngemm)
{
    const int bx = blockIdx.x;
    const int t  = threadIdx.x;

    if (bx >= ngemm) {
        // ---- pack role ----
        const int warp = t >> 5, lane = t & 31;
        const int r = (bx - ngemm) * 8 + warp;
        const int* row = adj + (size_t)r * NNODES;
        #pragma unroll
        for (int wg = 0; wg < 4; wg++) {
            uint32_t kept = 0;
            #pragma unroll
            for (int ww = 0; ww < 32; ww++) {
                int v = row[(wg * 32 + ww) * 32 + lane];
                uint32_t b = __ballot_sync(0xffffffffu, v > 0);
                if (lane == ww) kept = b;
            }
            maskb[(size_t)r * 128 + wg * 32 + lane] = kept;
        }
        return;
    }

    // ---- gemm role (4-stage cp.async, float4 inner loads) ----
    const int h  = bx >> 6;
    const int i0 = (bx & 63) * 64;
    const int dg = t & 15;
    const int ig = t >> 4;

    __shared__ float Xs[4][64][16];
    __shared__ float Ws[4][16][64];

    const float* Wh = W + (size_t)h * INDIM * HID;
    const int xrow = t >> 2, xseg = t & 3;
    const int wrow = t >> 4, wseg = t & 15;

    auto stage = [&](int buf, int kc) {
        cp16(&Xs[buf][xrow][xseg * 4], X + (size_t)(i0 + xrow) * INDIM + kc + xseg * 4);
        cp16(&Ws[buf][wrow][wseg * 4], Wh + (size_t)(kc + wrow) * HID + wseg * 4);
    };

    stage(0, 0);  CP_COMMIT();
    stage(1, 16); CP_COMMIT();
    stage(2, 32); CP_COMMIT();

    float acc[4][4] = {};
    #pragma unroll
    for (int kk = 0; kk < 16; kk++) {
        CP_WAIT(2);
        __syncthreads();
        if (kk + 3 < 16) stage((kk + 3) & 3, (kk + 3) * 16);
        CP_COMMIT();

        const int buf = kk & 3;
        #pragma unroll
        for (int k4 = 0; k4 < 4; k4++) {
            float4 wv0 = *(const float4*)(&Ws[buf][k4 * 4 + 0][dg * 4]);
            float4 wv1 = *(const float4*)(&Ws[buf][k4 * 4 + 1][dg * 4]);
            float4 wv2 = *(const float4*)(&Ws[buf][k4 * 4 + 2][dg * 4]);
            float4 wv3 = *(const float4*)(&Ws[buf][k4 * 4 + 3][dg * 4]);
            #pragma unroll
            for (int r = 0; r < 4; r++) {
                float4 x = *(const float4*)(&Xs[buf][ig * 4 + r][k4 * 4]);
                acc[r][0] += x.x * wv0.x; acc[r][1] += x.x * wv0.y; acc[r][2] += x.x * wv0.z; acc[r][3] += x.x * wv0.w;
                acc[r][0] += x.y * wv1.x; acc[r][1] += x.y * wv1.y; acc[r][2] += x.y * wv1.z; acc[r][3] += x.y * wv1.w;
                acc[r][0] += x.z * wv2.x; acc[r][1] += x.z * wv2.y; acc[r][2] += x.z * wv2.z; acc[r][3] += x.z * wv2.w;
                acc[r][0] += x.w * wv3.x; acc[r][1] += x.w * wv3.y; acc[r][2] += x.w * wv3.z; acc[r][3] += x.w * wv3.w;
            }
        }
    }

    // fold bias into acc
    float4 bv = *(const float4*)(B + h * HID + dg * 4);
    #pragma unroll
    for (int ii = 0; ii < 4; ii++) {
        acc[ii][0] += bv.x; acc[ii][1] += bv.y;
        acc[ii][2] += bv.z; acc[ii][3] += bv.w;
    }

    // src/dst projections: per-thread partial dot + 16-lane butterfly
    {
        float4 asv = *(const float4*)(Asrc + h * HID + dg * 4);
        float4 adv = *(const float4*)(Adst + h * HID + dg * 4);
        float sv[4], dvv[4];
        #pragma unroll
        for (int ii = 0; ii < 4; ii++) {
            sv[ii]  = acc[ii][0] * asv.x + acc[ii][1] * asv.y + acc[ii][2] * asv.z + acc[ii][3] * asv.w;
            dvv[ii] = acc[ii][0] * adv.x + acc[ii][1] * adv.y + acc[ii][2] * adv.z + acc[ii][3] * adv.w;
        }
        #pragma unroll
        for (int o = 1; o < 16; o <<= 1) {
            #pragma unroll
            for (int ii = 0; ii < 4; ii++) {
                sv[ii]  += __shfl_xor_sync(0xffffffffu, sv[ii], o);
                dvv[ii] += __shfl_xor_sync(0xffffffffu, dvv[ii], o);
            }
        }
        if (dg == 0) {
            const float abh = Ab[h];
            #pragma unroll
            for (int ii = 0; ii < 4; ii++) {
                const int gi = h * NNODES + i0 + ig * 4 + ii;
                float u = (sv[ii] + abh) * LOG2E;
                float v = dvv[ii] * LOG2E;
                srcP[gi] = u - SHIFT;
                srcQ[gi] = 0.2f * u - SHIFT;
                dstP[gi] = v;
                dstQ[gi] = 0.2f * v;
            }
        }
    }

    // paired f16 fragment tensor: [h][c64][ks][ntp][lane] uint4 (bias already in acc)
    uint32_t* fb = (uint32_t*)(YF + (size_t)h * 64 * 512);
    #pragma unroll
    for (int c = 0; c < 4; c++) {
        const int d = dg * 4 + c;
        const int ntp = d >> 4;
        const int sub = (d >> 3) & 1;
        const int lnb = (d & 7) * 4;
        #pragma unroll
        for (int p = 0; p < 2; p++) {
            const int jp = i0 + ig * 4 + 2 * p;
            const int c64 = jp >> 6;
            const int ks = (jp >> 4) & 3;
            const int rr = jp & 15;
            const int lanei = lnb + ((rr & 7) >> 1);
            const int word = sub * 2 + (rr >> 3);
            uint32_t val = pack_f16x2(acc[2 * p][c], acc[2 * p + 1][c]);
            size_t idx = (((size_t)c64 * 4 + ks) * 4 + ntp) * 32 + lanei;
            fb[idx * 4 + word] = val;
        }
    }
}

// ---------------- fused attention: 64-j chunks, 4-stage pipe, unroll x4 -------
__global__ void __launch_bounds__(256, 2) attn_mma_kernel(
    const uint4* __restrict__ whF,      // [H][64][4][4][32] uint4
    const float* __restrict__ srcP, const float* __restrict__ srcQ,  // [H][N]
    const float* __restrict__ dstP, const float* __restrict__ dstQ,  // [H][N]
    const uint32_t* __restrict__ maskb, // [N][128]
    float* __restrict__ pnum,           // [z][N][pcols]
    float* __restrict__ pden,           // [z][H][N]
    int pcols, int nheads)
{
    __shared__ alignas(16) uint4 bfragq[4][4][4][32];  // 4-stage, 8KB each
    __shared__ alignas(16) uint2 dsts2[1024];          // permuted (P2,Q2) j-pairs

    const int h    = blockIdx.y;
    const int t    = threadIdx.x;
    const int lane = t & 31;
    const int warp = t >> 5;
    const int gid  = lane >> 2;
    const int tig  = lane & 3;
    const int i0   = blockIdx.x * 128;
    const int z       = blockIdx.z;
    const int jsplit  = gridDim.z;
    const int nchunks = (NNODES / 64) / jsplit;
    const int jc0     = z * nchunks * 64;

    const int hN = h * NNODES;
    // stage dst pairs once, PERMUTED: within each 8-group, old m -> 2*(m&3)+(m>>2)
    // so reader (chunk,ks,tig) gets old {pidx, pidx+4} adjacent -> one LDS.128.
    for (int q = t; q < nchunks * 32; q += 256) {
        int j = jc0 + 2 * q;
        uint2 v;
        v.x = pack_f16x2(dstP[hN + j], dstP[hN + j + 1]);
        v.y = pack_f16x2(dstQ[hN + j], dstQ[hN + j + 1]);
        int m = q & 7;
        int pos = (q & ~7) | ((m & 3) << 1) | (m >> 2);
        dsts2[pos] = v;
    }

    const int iA = i0 + warp * 16 + gid;
    const int iB = iA + 8;
    const uint32_t srcP2A = pack_f16x2(srcP[hN + iA], srcP[hN + iA]);
    const uint32_t srcQ2A = pack_f16x2(srcQ[hN + iA], srcQ[hN + iA]);
    const uint32_t srcP2B = pack_f16x2(srcP[hN + iB], srcP[hN + iB]);
    const uint32_t srcQ2B = pack_f16x2(srcQ[hN + iB], srcQ[hN + iB]);
    const uint2* mA2 = (const uint2*)(maskb + (size_t)iA * 128 + (jc0 >> 5));
    const uint2* mB2 = (const uint2*)(maskb + (size_t)iB * 128 + (jc0 >> 5));

    const uint4* gsrc = whF + ((size_t)h * 64 + (jc0 >> 6)) * 512;

    float acc[9][4];
    #pragma unroll
    for (int n = 0; n < 9; n++)
        #pragma unroll
        for (int r = 0; r < 4; r++) acc[n][r] = 0.f;

    // prologue: stage chunks 0,1,2
    #pragma unroll
    for (int s = 0; s < 3; s++) {
        uint4* d0 = &bfragq[s][0][0][0];
        cp16(d0 + t, gsrc + (size_t)s * 512 + t);
        cp16(d0 + t + 256, gsrc + (size_t)s * 512 + t + 256);
        CP_COMMIT();
    }

    const int tshift = 2 * tig;
    for (int cg = 0; cg < nchunks; cg += 4) {
        // batched mask loads for 4 chunks
        uint4 mAa = *(const uint4*)(mA2 + cg);
        uint4 mAb = *(const uint4*)(mA2 + cg + 2);
        uint4 mBa = *(const uint4*)(mB2 + cg);
        uint4 mBb = *(const uint4*)(mB2 + cg + 2);
        uint32_t wAx[4] = {mAa.x, mAa.z, mAb.x, mAb.z};
        uint32_t wAy[4] = {mAa.y, mAa.w, mAb.y, mAb.w};
        uint32_t wBx[4] = {mBa.x, mBa.z, mBb.x, mBb.z};
        uint32_t wBy[4] = {mBa.y, mBa.w, mBb.y, mBb.w};

        #pragma unroll
        for (int cc = 0; cc < 4; cc++) {
            const int chunk = cg + cc;
            CP_WAIT(2);
            __syncthreads();
            if (chunk + 3 < nchunks) {
                uint4* dn = &bfragq[(cc + 3) & 3][0][0][0];
                const uint4* sn = gsrc + (size_t)(chunk + 3) * 512;
                cp16(dn + t, sn + t);
                cp16(dn + t + 256, sn + t + 256);
            }
            CP_COMMIT();

            #pragma unroll
            for (int ks = 0; ks < 4; ks++) {
                uint32_t pAm = ((ks < 2) ? wAx[cc] : wAy[cc]) >> ((ks & 1) * 16 + tshift);
                uint32_t pBm = ((ks < 2) ? wBx[cc] : wBy[cc]) >> ((ks & 1) * 16 + tshift);
                uint32_t sA1 = pAm << 7,  sA2 = pAm << 14;
                uint32_t sB1 = pBm << 7,  sB2 = pBm << 14;
                uint32_t mskA0 = prmt(sA1, sA2, 0xDD88u);
                uint32_t mskA1 = prmt(sA1, sA2, 0xEE99u);
                uint32_t mskB0 = prmt(sB1, sB2, 0xDD88u);
                uint32_t mskB1 = prmt(sB1, sB2, 0xEE99u);

                // one LDS.128: (P,Q) for j pairs (2tig,2tig+1) and (2tig+8,2tig+9)
                uint4 dd = *(const uint4*)(dsts2 + chunk * 32 + ks * 8 + tshift);

                uint32_t eA0 = hex2(hmax2(hadd2(srcP2A, dd.x), hadd2(srcQ2A, dd.y))) & mskA0;
                uint32_t eA1 = hex2(hmax2(hadd2(srcP2A, dd.z), hadd2(srcQ2A, dd.w))) & mskA1;
                uint32_t eB0 = hex2(hmax2(hadd2(srcP2B, dd.x), hadd2(srcQ2B, dd.y))) & mskB0;
                uint32_t eB1 = hex2(hmax2(hadd2(srcP2B, dd.z), hadd2(srcQ2B, dd.w))) & mskB1;

                const uint4* bk = &bfragq[cc][ks][0][lane];
                #pragma unroll
                for (int ntp = 0; ntp < 4; ntp++) {
                    uint4 b = bk[ntp * 32];
                    mma_f16(acc[2 * ntp],     eA0, eB0, eA1, eB1, b.x, b.y);
                    mma_f16(acc[2 * ntp + 1], eA0, eB0, eA1, eB1, b.z, b.w);
                }
                mma_f16(acc[8], eA0, eB0, eA1, eB1, ONES_F16X2, ONES_F16X2);
            }
        }
    }

    const float denA = acc[8][0];
    const float denB = acc[8][2];

    float* pA = pnum + ((size_t)z * NNODES + iA) * pcols + h * 64 + 2 * tig;
    float* pB = pnum + ((size_t)z * NNODES + iB) * pcols + h * 64 + 2 * tig;
    #pragma unroll
    for (int nt = 0; nt < 8; nt++) {
        float2 va, vb;
        va.x = acc[nt][0]; va.y = acc[nt][1];
        vb.x = acc[nt][2]; vb.y = acc[nt][3];
        *(float2*)(pA + nt * 8) = va;
        *(float2*)(pB + nt * 8) = vb;
    }
    if (tig == 0) {
        pden[((size_t)z * nheads + h) * NNODES + iA] = denA;
        pden[((size_t)z * nheads + h) * NNODES + iB] = denB;
    }
}

// ---------------- partial reduce + softmax divide + elu (templated ILP) -------
template<int ZN, int COLS, int CSHIFT, int H>
__global__ void reduce_kernel(const float* __restrict__ pnum,
                              const float* __restrict__ pden,
                              float* __restrict__ out)
{
    int idx = blockIdx.x * blockDim.x + threadIdx.x;
    int i = idx >> CSHIFT;
    int c = (idx & ((1 << CSHIFT) - 1)) << 3;
    int h = c >> 6;

    float den = 0.f;
    #pragma unroll
    for (int zz = 0; zz < ZN; zz++)
        den += pden[((size_t)zz * H + h) * NNODES + i];

    float4 a0, a1;
    {
        const float* p = pnum + (size_t)i * COLS + c;
        a0 = *(const float4*)p;
        a1 = *(const float4*)(p + 4);
    }
    #pragma unroll
    for (int zz = 1; zz < ZN; zz++) {
        const float* p = pnum + ((size_t)zz * NNODES + i) * COLS + c;
        float4 b0 = *(const float4*)p;
        float4 b1 = *(const float4*)(p + 4);
        a0.x += b0.x; a0.y += b0.y; a0.z += b0.z; a0.w += b0.w;
        a1.x += b1.x; a1.y += b1.y; a1.z += b1.z; a1.w += b1.w;
    }
    float inv = 1.f / den;
    float v[8] = {a0.x * inv, a0.y * inv, a0.z * inv, a0.w * inv,
                  a1.x * inv, a1.y * inv, a1.z * inv, a1.w * inv};
    #pragma unroll
    for (int r = 0; r < 8; r++) v[r] = (v[r] > 0.f) ? v[r] : expm1f(v[r]);
    float4 o0 = {v[0], v[1], v[2], v[3]};
    float4 o1 = {v[4], v[5], v[6], v[7]};
    float* op = out + (size_t)i * COLS + c;
    *(float4*)op = o0;
    *(float4*)(op + 4) = o1;
}

// ---------------- launch ------------------------------------------------------
extern "C" void kernel_launch(void* const* d_in, const int* in_sizes, int n_in,
                              void* d_out, int out_size)
{
    const float* h      = (const float*)d_in[0];
    const int*   adj    = (const int*)  d_in[1];
    const float* Wh     = (const float*)d_in[2];
    const float* bWh    = (const float*)d_in[3];
    const float* a_src  = (const float*)d_in[4];
    const float* a_dst  = (const float*)d_in[5];
    const float* a_b    = (const float*)d_in[6];
    const float* Wo     = (const float*)d_in[7];
    const float* bWo    = (const float*)d_in[8];
    const float* ao_src = (const float*)d_in[9];
    const float* ao_dst = (const float*)d_in[10];
    const float* ao_b   = (const float*)d_in[11];
    float* out = (float*)d_out;

    float *x2, *pnum, *pden;
    float *sP1, *sQ1, *dP1, *dQ1, *sP2, *sQ2, *dP2, *dQ2;
    uint32_t* maskb;
    uint4 *whF1, *whF2;
    cudaGetSymbolAddress((void**)&x2,   g_x2);
    cudaGetSymbolAddress((void**)&sP1, g_srcP1);
    cudaGetSymbolAddress((void**)&sQ1, g_srcQ1);
    cudaGetSymbolAddress((void**)&dP1, g_dstP1);
    cudaGetSymbolAddress((void**)&dQ1, g_dstQ1);
    cudaGetSymbolAddress((void**)&sP2, g_srcP2);
    cudaGetSymbolAddress((void**)&sQ2, g_srcQ2);
    cudaGetSymbolAddress((void**)&dP2, g_dstP2);
    cudaGetSymbolAddress((void**)&dQ2, g_dstQ2);
    cudaGetSymbolAddress((void**)&pnum, g_pnum);
    cudaGetSymbolAddress((void**)&pden, g_pden);
    cudaGetSymbolAddress((void**)&maskb, g_mask);
    cudaGetSymbolAddress((void**)&whF1, g_whF1);
    cudaGetSymbolAddress((void**)&whF2, g_whF2);

    // Layer 1: gemm+srcdst (256 blocks) + pack (512 blocks) fused
    fused_gemm_pack_kernel<<<256 + 512, 256>>>(h, Wh, bWh, whF1,
                                               a_src, a_dst, a_b,
                                               sP1, sQ1, dP1, dQ1,
                                               adj, maskb, 256);
    attn_mma_kernel<<<dim3(NNODES / 128, 4, 2), 256>>>(whF1, sP1, sQ1, dP1, dQ1, maskb, pnum, pden, 256, 4);
    reduce_kernel<2, 256, 5, 4><<<(NNODES * 32) / 256, 256>>>(pnum, pden, x2);

    // Layer 2 (jsplit=8)
    fused_gemm_pack_kernel<<<64, 256>>>(x2, Wo, bWo, whF2,
                                        ao_src, ao_dst, ao_b,
                                        sP2, sQ2, dP2, dQ2,
                                        adj, maskb, 64);
    attn_mma_kernel<<<dim3(NNODES / 128, 1, 8), 256>>>(whF2, sP2, sQ2, dP2, dQ2, maskb, pnum, pden, 64, 1);
    reduce_kernel<8, 64, 3, 1><<<(NNODES * 8) / 256, 256>>>(pnum, pden, out);
}